// round 6
// baseline (speedup 1.0000x reference)
#include <cuda_runtime.h>
#include <cuda_bf16.h>
#include <cstdint>

#define N_NODES 100000
#define N_EDGES 800000
#define F_IN    256
#define HID     128
#define CLS     32
#define SCAN_B  512
#define N_SBLK  ((N_NODES + SCAN_B - 1) / SCAN_B)   // 196

// ---------------- scratch (device globals: no allocation allowed) ----------
__device__ int   g_cnt[N_NODES];        // in-degree (edges only)
__device__ float g_dinv[N_NODES];
__device__ int   g_rowptr[N_NODES + 1];
__device__ int   g_cursor[N_NODES];
__device__ int   g_col[N_EDGES];        // src ids grouped by dst
__device__ int   g_bsum[N_SBLK];
__device__ int   g_boff[N_SBLK];
__device__ float g_q1 [(size_t)N_NODES * HID];   // xw1 * dinv[row]
__device__ float g_h1 [(size_t)N_NODES * HID];
__device__ float g_q2 [(size_t)N_NODES * CLS];   // xw2 * dinv[row]
__device__ int   g_is64;

// ---------------- helpers ----------------------------------------------------
__device__ __forceinline__ uint32_t smem_addr(const void* p) {
    return (uint32_t)__cvta_generic_to_shared(p);
}
#define LDSM_X4(r, a)                                                          \
    asm volatile("ldmatrix.sync.aligned.m8n8.x4.shared.b16 {%0,%1,%2,%3}, [%4];" \
                 : "=r"((r)[0]), "=r"((r)[1]), "=r"((r)[2]), "=r"((r)[3])      \
                 : "r"(a))
#define LDSM_X2T(r, a)                                                         \
    asm volatile("ldmatrix.sync.aligned.m8n8.x2.trans.shared.b16 {%0,%1}, [%2];" \
                 : "=r"((r)[0]), "=r"((r)[1]) : "r"(a))
#define MMA_BF16(c, a, b)                                                      \
    asm volatile("mma.sync.aligned.m16n8k16.row.col.f32.bf16.bf16.f32 "        \
                 "{%0,%1,%2,%3}, {%4,%5,%6,%7}, {%8,%9}, {%0,%1,%2,%3};"       \
                 : "+f"((c)[0]), "+f"((c)[1]), "+f"((c)[2]), "+f"((c)[3])      \
                 : "r"((a)[0]), "r"((a)[1]), "r"((a)[2]), "r"((a)[3]),         \
                   "r"((b)[0]), "r"((b)[1]))

// ---------------- edge-index dtype probe ------------------------------------
__global__ void k_detect(const int* __restrict__ ei) {
    if (blockIdx.x == 0 && threadIdx.x == 0) {
        int is64 = 1;
        for (int i = 0; i < 64; i++)
            if (ei[2 * i + 1] != 0) { is64 = 0; break; }
        g_is64 = is64;
    }
}
__device__ __forceinline__ int edge_at(const int* __restrict__ ei,
                                       int which, int e, int is64) {
    size_t base = (size_t)which * N_EDGES + (size_t)e;
    return is64 ? ei[base * 2] : ei[base];
}

// ---------------- degree count + norm ---------------------------------------
__global__ void k_zero_cnt() {
    int i = blockIdx.x * blockDim.x + threadIdx.x;
    if (i < N_NODES) g_cnt[i] = 0;
}
__global__ void k_cnt_scatter(const int* __restrict__ ei) {
    int e = blockIdx.x * blockDim.x + threadIdx.x;
    if (e >= N_EDGES) return;
    atomicAdd(&g_cnt[edge_at(ei, 1, e, g_is64)], 1);
}
__global__ void k_dinv() {
    int i = blockIdx.x * blockDim.x + threadIdx.x;
    if (i < N_NODES) g_dinv[i] = rsqrtf((float)(g_cnt[i] + 1));  // +1 self loop
}

// ---------------- CSR build: 3-phase scan + fill ----------------------------
__global__ void k_scan1() {
    __shared__ int sh[SCAN_B];
    int t = threadIdx.x;
    int i = blockIdx.x * SCAN_B + t;
    int v = (i < N_NODES) ? g_cnt[i] : 0;
    sh[t] = v;
    __syncthreads();
#pragma unroll
    for (int off = 1; off < SCAN_B; off <<= 1) {
        int x = (t >= off) ? sh[t - off] : 0;
        __syncthreads();
        sh[t] += x;
        __syncthreads();
    }
    if (i < N_NODES) g_rowptr[i] = sh[t] - v;   // exclusive
    if (t == SCAN_B - 1) g_bsum[blockIdx.x] = sh[t];
}
__global__ void k_scan2() {
    __shared__ int sh[256];
    int t = threadIdx.x;
    int v = (t < N_SBLK) ? g_bsum[t] : 0;
    sh[t] = v;
    __syncthreads();
#pragma unroll
    for (int off = 1; off < 256; off <<= 1) {
        int x = (t >= off) ? sh[t - off] : 0;
        __syncthreads();
        sh[t] += x;
        __syncthreads();
    }
    if (t < N_SBLK) g_boff[t] = sh[t] - v;      // exclusive
}
__global__ void k_scan3() {
    int i = blockIdx.x * blockDim.x + threadIdx.x;
    if (i < N_NODES) {
        int rp = g_rowptr[i] + g_boff[i / SCAN_B];
        g_rowptr[i] = rp;
        g_cursor[i] = rp;
    }
    if (i == 0) g_rowptr[N_NODES] = N_EDGES;
}
__global__ void k_fill(const int* __restrict__ ei) {
    int e = blockIdx.x * blockDim.x + threadIdx.x;
    if (e >= N_EDGES) return;
    int is64 = g_is64;
    int s = edge_at(ei, 0, e, is64);
    int d = edge_at(ei, 1, e, is64);
    int pos = atomicAdd(&g_cursor[d], 1);
    g_col[pos] = s;
}

// ---------------- layer-1 GEMM: mma.sync bf16-split (3xMMA) -----------------
// q1 = (X @ W1) * dinv[row]
#define BM 128
#define BN 128
#define BK 32
#define APAD 8
#define BPAD 8

__global__ __launch_bounds__(256, 1) void gemm1_mma(const float* __restrict__ X,
                                                    const float* __restrict__ W1) {
    __shared__ __align__(16) __nv_bfloat16 sAh[BM][BK + APAD];
    __shared__ __align__(16) __nv_bfloat16 sAl[BM][BK + APAD];
    __shared__ __align__(16) __nv_bfloat16 sBh[BK][BN + BPAD];
    __shared__ __align__(16) __nv_bfloat16 sBl[BK][BN + BPAD];

    const int tid  = threadIdx.x;
    const int lane = tid & 31;
    const int wid  = tid >> 5;
    const int wm   = wid >> 2;
    const int wn   = wid & 3;
    const int rowBase = blockIdx.x * BM;

    float acc[4][4][4];
#pragma unroll
    for (int mi = 0; mi < 4; mi++)
#pragma unroll
        for (int ni = 0; ni < 4; ni++)
#pragma unroll
            for (int r = 0; r < 4; r++) acc[mi][ni][r] = 0.f;

    for (int kt = 0; kt < F_IN; kt += BK) {
#pragma unroll
        for (int i = 0; i < 4; i++) {
            int idx = tid + i * 256;
            int r = idx >> 3, c4 = (idx & 7) * 4;
            int gr = rowBase + r;
            float4 v = make_float4(0.f, 0.f, 0.f, 0.f);
            if (gr < N_NODES)
                v = *(const float4*)(X + (size_t)gr * F_IN + kt + c4);
#pragma unroll
            for (int j = 0; j < 4; j++) {
                float x = (&v.x)[j];
                __nv_bfloat16 hi = __float2bfloat16(x);
                __nv_bfloat16 lo = __float2bfloat16(x - __bfloat162float(hi));
                sAh[r][c4 + j] = hi;
                sAl[r][c4 + j] = lo;
            }
        }
#pragma unroll
        for (int i = 0; i < 4; i++) {
            int idx = tid + i * 256;
            int k = idx >> 5, n4 = (idx & 31) * 4;
            float4 w = *(const float4*)(W1 + (size_t)(kt + k) * HID + n4);
#pragma unroll
            for (int j = 0; j < 4; j++) {
                float x = (&w.x)[j];
                __nv_bfloat16 hi = __float2bfloat16(x);
                __nv_bfloat16 lo = __float2bfloat16(x - __bfloat162float(hi));
                sBh[k][n4 + j] = hi;
                sBl[k][n4 + j] = lo;
            }
        }
        __syncthreads();

#pragma unroll
        for (int ks = 0; ks < BK / 16; ks++) {
            int k16 = ks * 16;
            uint32_t ah[4][4], al[4][4], bh[4][2], bl[4][2];
#pragma unroll
            for (int mi = 0; mi < 4; mi++) {
                int row = wm * 64 + mi * 16 + (lane & 15);
                int col = k16 + (lane >> 4) * 8;
                LDSM_X4(ah[mi], smem_addr(&sAh[row][col]));
                LDSM_X4(al[mi], smem_addr(&sAl[row][col]));
            }
#pragma unroll
            for (int ni = 0; ni < 4; ni++) {
                int krow = k16 + (lane & 15);
                int col  = wn * 32 + ni * 8;
                LDSM_X2T(bh[ni], smem_addr(&sBh[krow][col]));
                LDSM_X2T(bl[ni], smem_addr(&sBl[krow][col]));
            }
#pragma unroll
            for (int mi = 0; mi < 4; mi++)
#pragma unroll
                for (int ni = 0; ni < 4; ni++) {
                    MMA_BF16(acc[mi][ni], ah[mi], bh[ni]);
                    MMA_BF16(acc[mi][ni], ah[mi], bl[ni]);
                    MMA_BF16(acc[mi][ni], al[mi], bh[ni]);
                }
        }
        __syncthreads();
    }

    const int rBase = rowBase + wm * 64 + (lane >> 2);
    const int cBase = wn * 32 + (lane & 3) * 2;
#pragma unroll
    for (int mi = 0; mi < 4; mi++) {
        int gr0 = rBase + mi * 16;
        int gr1 = gr0 + 8;
        float d0 = (gr0 < N_NODES) ? g_dinv[gr0] : 0.f;
        float d1 = (gr1 < N_NODES) ? g_dinv[gr1] : 0.f;
#pragma unroll
        for (int ni = 0; ni < 4; ni++) {
            int gc = cBase + ni * 8;
            if (gr0 < N_NODES)
                *(float2*)(g_q1 + (size_t)gr0 * HID + gc) =
                    make_float2(acc[mi][ni][0] * d0, acc[mi][ni][1] * d0);
            if (gr1 < N_NODES)
                *(float2*)(g_q1 + (size_t)gr1 * HID + gc) =
                    make_float2(acc[mi][ni][2] * d1, acc[mi][ni][3] * d1);
        }
    }
}

// ---------------- CSR aggregation layer 1 (fused bias+relu) -----------------
// h1[i] = relu(dinv[i] * (q1[i] + sum_{e} q1[col[e]]) + b1)
__global__ void k_agg1(const float* __restrict__ b1) {
    int node = blockIdx.x * (blockDim.x >> 5) + (threadIdx.x >> 5);
    int lane = threadIdx.x & 31;
    if (node >= N_NODES) return;
    int start = g_rowptr[node];
    int end   = g_rowptr[node + 1];

    float4 acc = ((const float4*)(g_q1 + (size_t)node * HID))[lane];  // self
    int e = start;
    for (; e + 1 < end; e += 2) {       // 2-way unroll for MLP
        int s0 = g_col[e], s1 = g_col[e + 1];
        float4 v0 = ((const float4*)(g_q1 + (size_t)s0 * HID))[lane];
        float4 v1 = ((const float4*)(g_q1 + (size_t)s1 * HID))[lane];
        acc.x += v0.x + v1.x; acc.y += v0.y + v1.y;
        acc.z += v0.z + v1.z; acc.w += v0.w + v1.w;
    }
    if (e < end) {
        int s = g_col[e];
        float4 v = ((const float4*)(g_q1 + (size_t)s * HID))[lane];
        acc.x += v.x; acc.y += v.y; acc.z += v.z; acc.w += v.w;
    }
    float d = g_dinv[node];
    float4 b = ((const float4*)b1)[lane];
    float4 o;
    o.x = fmaxf(fmaf(acc.x, d, b.x), 0.f);
    o.y = fmaxf(fmaf(acc.y, d, b.y), 0.f);
    o.z = fmaxf(fmaf(acc.z, d, b.z), 0.f);
    o.w = fmaxf(fmaf(acc.w, d, b.w), 0.f);
    ((float4*)(g_h1 + (size_t)node * HID))[lane] = o;
}

// ---------------- SIMT SGEMM layer 2: q2 = (h1 @ W2) * dinv[row] ------------
template<int TBM, int TBN, int TBK, int TM, int TN>
__global__ void sgemm2_kernel(const float* __restrict__ A,
                              const float* __restrict__ B,
                              float* __restrict__ Q,
                              const float* __restrict__ dinv,
                              int M, int N, int K) {
    constexpr int THREADS = (TBM / TM) * (TBN / TN);
    __shared__ float As[TBK][TBM];
    __shared__ float Bs[TBK][TBN];

    const int tid = threadIdx.x;
    const int tx  = tid % (TBN / TN);
    const int ty  = tid / (TBN / TN);
    const int rowBase = blockIdx.y * TBM;
    const int colBase = blockIdx.x * TBN;

    float acc[TM][TN];
#pragma unroll
    for (int i = 0; i < TM; i++)
#pragma unroll
        for (int j = 0; j < TN; j++) acc[i][j] = 0.0f;

    for (int kt = 0; kt < K; kt += TBK) {
#pragma unroll
        for (int idx = tid; idx < TBM * TBK / 4; idx += THREADS) {
            int r = idx / (TBK / 4);
            int c = (idx % (TBK / 4)) * 4;
            int gr = rowBase + r;
            float4 v = make_float4(0.f, 0.f, 0.f, 0.f);
            if (gr < M) v = *(const float4*)(A + (size_t)gr * K + kt + c);
            As[c + 0][r] = v.x; As[c + 1][r] = v.y;
            As[c + 2][r] = v.z; As[c + 3][r] = v.w;
        }
#pragma unroll
        for (int idx = tid; idx < TBK * TBN / 4; idx += THREADS) {
            int r = idx / (TBN / 4);
            int c = (idx % (TBN / 4)) * 4;
            int gc = colBase + c;
            float4 v = make_float4(0.f, 0.f, 0.f, 0.f);
            if (gc < N) v = *(const float4*)(B + (size_t)(kt + r) * N + gc);
            *(float4*)&Bs[r][c] = v;
        }
        __syncthreads();
#pragma unroll
        for (int k = 0; k < TBK; k++) {
            float ra[TM], rb[TN];
#pragma unroll
            for (int i = 0; i < TM; i++) ra[i] = As[k][ty * TM + i];
#pragma unroll
            for (int j = 0; j < TN; j++) rb[j] = Bs[k][tx * TN + j];
#pragma unroll
            for (int i = 0; i < TM; i++)
#pragma unroll
                for (int j = 0; j < TN; j++)
                    acc[i][j] += ra[i] * rb[j];
        }
        __syncthreads();
    }

#pragma unroll
    for (int i = 0; i < TM; i++) {
        int gr = rowBase + ty * TM + i;
        if (gr >= M) continue;
        float d = dinv[gr];
#pragma unroll
        for (int j = 0; j < TN; j++) {
            int gc = colBase + tx * TN + j;
            if (gc < N) Q[(size_t)gr * N + gc] = acc[i][j] * d;
        }
    }
}

// ---------------- CSR aggregation layer 2 (fused bias+logsoftmax) -----------
__global__ void k_agg2(const float* __restrict__ b2,
                       float* __restrict__ out) {
    int node = blockIdx.x * (blockDim.x >> 5) + (threadIdx.x >> 5);
    int lane = threadIdx.x & 31;
    if (node >= N_NODES) return;
    int start = g_rowptr[node];
    int end   = g_rowptr[node + 1];

    float acc = g_q2[(size_t)node * CLS + lane];   // self
    int e = start;
    for (; e + 1 < end; e += 2) {
        int s0 = g_col[e], s1 = g_col[e + 1];
        acc += g_q2[(size_t)s0 * CLS + lane] + g_q2[(size_t)s1 * CLS + lane];
    }
    if (e < end) acc += g_q2[(size_t)g_col[e] * CLS + lane];

    float v = fmaf(acc, g_dinv[node], b2[lane]);
    float m = v;
#pragma unroll
    for (int o = 16; o > 0; o >>= 1) m = fmaxf(m, __shfl_xor_sync(0xffffffffu, m, o));
    float ex = __expf(v - m);
    float ssum = ex;
#pragma unroll
    for (int o = 16; o > 0; o >>= 1) ssum += __shfl_xor_sync(0xffffffffu, ssum, o);
    out[(size_t)node * CLS + lane] = v - m - __logf(ssum);
}

// ---------------- launch -----------------------------------------------------
extern "C" void kernel_launch(void* const* d_in, const int* in_sizes, int n_in,
                              void* d_out, int out_size) {
    const float* X   = (const float*)d_in[0];
    const int*   ei  = (const int*)d_in[1];
    const float* W1  = (const float*)d_in[2];
    const float* b1  = (const float*)d_in[3];
    const float* W2  = (const float*)d_in[4];
    const float* b2  = (const float*)d_in[5];
    float*       out = (float*)d_out;

    float *p_h1 = nullptr, *p_q2 = nullptr, *p_dinv = nullptr;
    cudaGetSymbolAddress((void**)&p_h1,   g_h1);
    cudaGetSymbolAddress((void**)&p_q2,   g_q2);
    cudaGetSymbolAddress((void**)&p_dinv, g_dinv);

    const int TB = 256;
    const int nodeGrid = (N_NODES + TB - 1) / TB;
    const int edgeGrid = (N_EDGES + TB - 1) / TB;

    // degree + norm + CSR
    k_detect     <<<1, 32>>>(ei);
    k_zero_cnt   <<<nodeGrid, TB>>>();
    k_cnt_scatter<<<edgeGrid, TB>>>(ei);
    k_dinv       <<<nodeGrid, TB>>>();
    k_scan1      <<<N_SBLK, SCAN_B>>>();
    k_scan2      <<<1, 256>>>();
    k_scan3      <<<nodeGrid, TB>>>();
    k_fill       <<<edgeGrid, TB>>>(ei);

    // layer 1
    gemm1_mma<<<(N_NODES + BM - 1) / BM, 256>>>(X, W1);
    k_agg1   <<<(N_NODES * 32 + TB - 1) / TB, TB>>>(b1);

    // layer 2
    {
        dim3 grid(CLS / 32, (N_NODES + 127) / 128);
        sgemm2_kernel<128, 32, 32, 8, 2><<<grid, 256>>>(p_h1, W2, p_q2,
                                                        p_dinv, N_NODES, CLS, HID);
    }
    k_agg2<<<(N_NODES * 32 + TB - 1) / TB, TB>>>(b2, out);
}

// round 7
// speedup vs baseline: 1.3274x; 1.3274x over previous
#include <cuda_runtime.h>
#include <cuda_bf16.h>
#include <cstdint>

#define N_NODES 100000
#define N_EDGES 800000
#define F_IN    256
#define HID     128
#define CLS     32
#define SCAN_B  512
#define N_SBLK  ((N_NODES + SCAN_B - 1) / SCAN_B)   // 196

// ---------------- scratch (device globals: no allocation allowed) ----------
__device__ int   g_cnt[N_NODES];
__device__ float g_dinv[N_NODES];
__device__ int   g_rowptr[N_NODES + 1];
__device__ int   g_cursor[N_NODES];
__device__ int   g_col[N_EDGES];
__device__ int   g_bsum[N_SBLK];
__device__ int   g_boff[N_SBLK];
__device__ float g_q1 [(size_t)N_NODES * HID];
__device__ float g_h1 [(size_t)N_NODES * HID];
__device__ float g_q2 [(size_t)N_NODES * CLS];
__device__ int   g_is64;

// ---------------- helpers ----------------------------------------------------
__device__ __forceinline__ uint32_t smem_addr(const void* p) {
    return (uint32_t)__cvta_generic_to_shared(p);
}
#define LDSM_X4(r, a)                                                          \
    asm volatile("ldmatrix.sync.aligned.m8n8.x4.shared.b16 {%0,%1,%2,%3}, [%4];" \
                 : "=r"((r)[0]), "=r"((r)[1]), "=r"((r)[2]), "=r"((r)[3])      \
                 : "r"(a))
#define LDSM_X2T(r, a)                                                         \
    asm volatile("ldmatrix.sync.aligned.m8n8.x2.trans.shared.b16 {%0,%1}, [%2];" \
                 : "=r"((r)[0]), "=r"((r)[1]) : "r"(a))
#define MMA_BF16(c, a, b)                                                      \
    asm volatile("mma.sync.aligned.m16n8k16.row.col.f32.bf16.bf16.f32 "        \
                 "{%0,%1,%2,%3}, {%4,%5,%6,%7}, {%8,%9}, {%0,%1,%2,%3};"       \
                 : "+f"((c)[0]), "+f"((c)[1]), "+f"((c)[2]), "+f"((c)[3])      \
                 : "r"((a)[0]), "r"((a)[1]), "r"((a)[2]), "r"((a)[3]),         \
                   "r"((b)[0]), "r"((b)[1]))

// ---------------- edge-index dtype probe ------------------------------------
__global__ void k_detect(const int* __restrict__ ei) {
    if (blockIdx.x == 0 && threadIdx.x == 0) {
        int is64 = 1;
        for (int i = 0; i < 64; i++)
            if (ei[2 * i + 1] != 0) { is64 = 0; break; }
        g_is64 = is64;
    }
}
__device__ __forceinline__ int edge_at(const int* __restrict__ ei,
                                       int which, int e, int is64) {
    size_t base = (size_t)which * N_EDGES + (size_t)e;
    return is64 ? ei[base * 2] : ei[base];
}

// ---------------- degree count ----------------------------------------------
__global__ void k_zero_cnt() {
    int i = blockIdx.x * blockDim.x + threadIdx.x;
    if (i < N_NODES) g_cnt[i] = 0;
}
__global__ void k_cnt_scatter(const int* __restrict__ ei) {
    int e = blockIdx.x * blockDim.x + threadIdx.x;
    if (e >= N_EDGES) return;
    atomicAdd(&g_cnt[edge_at(ei, 1, e, g_is64)], 1);
}

// ---------------- CSR build: 3-phase scan (+dinv fused) + fill --------------
__global__ void k_scan1() {
    __shared__ int sh[SCAN_B];
    int t = threadIdx.x;
    int i = blockIdx.x * SCAN_B + t;
    int v = (i < N_NODES) ? g_cnt[i] : 0;
    sh[t] = v;
    __syncthreads();
#pragma unroll
    for (int off = 1; off < SCAN_B; off <<= 1) {
        int x = (t >= off) ? sh[t - off] : 0;
        __syncthreads();
        sh[t] += x;
        __syncthreads();
    }
    if (i < N_NODES) g_rowptr[i] = sh[t] - v;   // exclusive (within block)
    if (t == SCAN_B - 1) g_bsum[blockIdx.x] = sh[t];
}
__global__ void k_scan2() {
    __shared__ int sh[256];
    int t = threadIdx.x;
    int v = (t < N_SBLK) ? g_bsum[t] : 0;
    sh[t] = v;
    __syncthreads();
#pragma unroll
    for (int off = 1; off < 256; off <<= 1) {
        int x = (t >= off) ? sh[t - off] : 0;
        __syncthreads();
        sh[t] += x;
        __syncthreads();
    }
    if (t < N_SBLK) g_boff[t] = sh[t] - v;      // exclusive
}
__global__ void k_scan3() {
    int i = blockIdx.x * blockDim.x + threadIdx.x;
    if (i < N_NODES) {
        int rp = g_rowptr[i] + g_boff[i / SCAN_B];
        g_rowptr[i] = rp;
        g_cursor[i] = rp;
        g_dinv[i]   = rsqrtf((float)(g_cnt[i] + 1));   // +1 self loop
    }
    if (i == 0) g_rowptr[N_NODES] = N_EDGES;
}
__global__ void k_fill(const int* __restrict__ ei) {
    int e = blockIdx.x * blockDim.x + threadIdx.x;
    if (e >= N_EDGES) return;
    int is64 = g_is64;
    int s = edge_at(ei, 0, e, is64);
    int d = edge_at(ei, 1, e, is64);
    int pos = atomicAdd(&g_cursor[d], 1);
    g_col[pos] = s;
}

// ---------------- layer-1 GEMM: mma.sync bf16-split (3xMMA) -----------------
// q1 = (X @ W1) * dinv[row]
#define BM 128
#define BN 128
#define BK 32
#define APAD 8
#define BPAD 8

__global__ __launch_bounds__(256, 1) void gemm1_mma(const float* __restrict__ X,
                                                    const float* __restrict__ W1) {
    __shared__ __align__(16) __nv_bfloat16 sAh[BM][BK + APAD];
    __shared__ __align__(16) __nv_bfloat16 sAl[BM][BK + APAD];
    __shared__ __align__(16) __nv_bfloat16 sBh[BK][BN + BPAD];
    __shared__ __align__(16) __nv_bfloat16 sBl[BK][BN + BPAD];

    const int tid  = threadIdx.x;
    const int lane = tid & 31;
    const int wid  = tid >> 5;
    const int wm   = wid >> 2;
    const int wn   = wid & 3;
    const int rowBase = blockIdx.x * BM;

    float acc[4][4][4];
#pragma unroll
    for (int mi = 0; mi < 4; mi++)
#pragma unroll
        for (int ni = 0; ni < 4; ni++)
#pragma unroll
            for (int r = 0; r < 4; r++) acc[mi][ni][r] = 0.f;

    for (int kt = 0; kt < F_IN; kt += BK) {
#pragma unroll
        for (int i = 0; i < 4; i++) {
            int idx = tid + i * 256;
            int r = idx >> 3, c4 = (idx & 7) * 4;
            int gr = rowBase + r;
            float4 v = make_float4(0.f, 0.f, 0.f, 0.f);
            if (gr < N_NODES)
                v = *(const float4*)(X + (size_t)gr * F_IN + kt + c4);
#pragma unroll
            for (int j = 0; j < 4; j++) {
                float x = (&v.x)[j];
                __nv_bfloat16 hi = __float2bfloat16(x);
                __nv_bfloat16 lo = __float2bfloat16(x - __bfloat162float(hi));
                sAh[r][c4 + j] = hi;
                sAl[r][c4 + j] = lo;
            }
        }
#pragma unroll
        for (int i = 0; i < 4; i++) {
            int idx = tid + i * 256;
            int k = idx >> 5, n4 = (idx & 31) * 4;
            float4 w = *(const float4*)(W1 + (size_t)(kt + k) * HID + n4);
#pragma unroll
            for (int j = 0; j < 4; j++) {
                float x = (&w.x)[j];
                __nv_bfloat16 hi = __float2bfloat16(x);
                __nv_bfloat16 lo = __float2bfloat16(x - __bfloat162float(hi));
                sBh[k][n4 + j] = hi;
                sBl[k][n4 + j] = lo;
            }
        }
        __syncthreads();

#pragma unroll
        for (int ks = 0; ks < BK / 16; ks++) {
            int k16 = ks * 16;
            uint32_t ah[4][4], al[4][4], bh[4][2], bl[4][2];
#pragma unroll
            for (int mi = 0; mi < 4; mi++) {
                int row = wm * 64 + mi * 16 + (lane & 15);
                int col = k16 + (lane >> 4) * 8;
                LDSM_X4(ah[mi], smem_addr(&sAh[row][col]));
                LDSM_X4(al[mi], smem_addr(&sAl[row][col]));
            }
#pragma unroll
            for (int ni = 0; ni < 4; ni++) {
                int krow = k16 + (lane & 15);
                int col  = wn * 32 + ni * 8;
                LDSM_X2T(bh[ni], smem_addr(&sBh[krow][col]));
                LDSM_X2T(bl[ni], smem_addr(&sBl[krow][col]));
            }
#pragma unroll
            for (int mi = 0; mi < 4; mi++)
#pragma unroll
                for (int ni = 0; ni < 4; ni++) {
                    MMA_BF16(acc[mi][ni], ah[mi], bh[ni]);
                    MMA_BF16(acc[mi][ni], ah[mi], bl[ni]);
                    MMA_BF16(acc[mi][ni], al[mi], bh[ni]);
                }
        }
        __syncthreads();
    }

    const int rBase = rowBase + wm * 64 + (lane >> 2);
    const int cBase = wn * 32 + (lane & 3) * 2;
#pragma unroll
    for (int mi = 0; mi < 4; mi++) {
        int gr0 = rBase + mi * 16;
        int gr1 = gr0 + 8;
        float d0 = (gr0 < N_NODES) ? g_dinv[gr0] : 0.f;
        float d1 = (gr1 < N_NODES) ? g_dinv[gr1] : 0.f;
#pragma unroll
        for (int ni = 0; ni < 4; ni++) {
            int gc = cBase + ni * 8;
            if (gr0 < N_NODES)
                *(float2*)(g_q1 + (size_t)gr0 * HID + gc) =
                    make_float2(acc[mi][ni][0] * d0, acc[mi][ni][1] * d0);
            if (gr1 < N_NODES)
                *(float2*)(g_q1 + (size_t)gr1 * HID + gc) =
                    make_float2(acc[mi][ni][2] * d1, acc[mi][ni][3] * d1);
        }
    }
}

// ---------------- CSR aggregation layer 1 (index-prefetch gather) -----------
// h1[i] = relu(dinv[i] * (q1[i] + sum_e q1[col[e]]) + b1)
__global__ void k_agg1(const float* __restrict__ b1) {
    int node = blockIdx.x * (blockDim.x >> 5) + (threadIdx.x >> 5);
    int lane = threadIdx.x & 31;
    if (node >= N_NODES) return;
    int start = g_rowptr[node];
    int deg   = g_rowptr[node + 1] - start;

    const float4* q1v = (const float4*)g_q1;
    float4 acc = q1v[(size_t)node * 32 + lane];      // self term

    // prefetch up to 32 indices in ONE coalesced read; broadcast via shfl
    int myidx = (lane < deg) ? g_col[start + lane] : 0;
    int n32 = deg < 32 ? deg : 32;
    int e = 0;
    for (; e + 4 <= n32; e += 4) {
        int s0 = __shfl_sync(0xffffffffu, myidx, e);
        int s1 = __shfl_sync(0xffffffffu, myidx, e + 1);
        int s2 = __shfl_sync(0xffffffffu, myidx, e + 2);
        int s3 = __shfl_sync(0xffffffffu, myidx, e + 3);
        float4 v0 = q1v[(size_t)s0 * 32 + lane];
        float4 v1 = q1v[(size_t)s1 * 32 + lane];
        float4 v2 = q1v[(size_t)s2 * 32 + lane];
        float4 v3 = q1v[(size_t)s3 * 32 + lane];
        acc.x += (v0.x + v1.x) + (v2.x + v3.x);
        acc.y += (v0.y + v1.y) + (v2.y + v3.y);
        acc.z += (v0.z + v1.z) + (v2.z + v3.z);
        acc.w += (v0.w + v1.w) + (v2.w + v3.w);
    }
    for (; e < n32; e++) {
        int s = __shfl_sync(0xffffffffu, myidx, e);
        float4 v = q1v[(size_t)s * 32 + lane];
        acc.x += v.x; acc.y += v.y; acc.z += v.z; acc.w += v.w;
    }
    for (e = 32; e < deg; e++) {                     // rare high-degree tail
        int s = g_col[start + e];
        float4 v = q1v[(size_t)s * 32 + lane];
        acc.x += v.x; acc.y += v.y; acc.z += v.z; acc.w += v.w;
    }

    float d = g_dinv[node];
    float4 b = ((const float4*)b1)[lane];
    float4 o;
    o.x = fmaxf(fmaf(acc.x, d, b.x), 0.f);
    o.y = fmaxf(fmaf(acc.y, d, b.y), 0.f);
    o.z = fmaxf(fmaf(acc.z, d, b.z), 0.f);
    o.w = fmaxf(fmaf(acc.w, d, b.w), 0.f);
    ((float4*)(g_h1 + (size_t)node * HID))[lane] = o;
}

// ---------------- SIMT SGEMM layer 2: q2 = (h1 @ W2) * dinv[row] ------------
template<int TBM, int TBN, int TBK, int TM, int TN>
__global__ void sgemm2_kernel(const float* __restrict__ A,
                              const float* __restrict__ B,
                              float* __restrict__ Q,
                              const float* __restrict__ dinv,
                              int M, int N, int K) {
    constexpr int THREADS = (TBM / TM) * (TBN / TN);
    __shared__ float As[TBK][TBM];
    __shared__ float Bs[TBK][TBN];

    const int tid = threadIdx.x;
    const int tx  = tid % (TBN / TN);
    const int ty  = tid / (TBN / TN);
    const int rowBase = blockIdx.y * TBM;
    const int colBase = blockIdx.x * TBN;

    float acc[TM][TN];
#pragma unroll
    for (int i = 0; i < TM; i++)
#pragma unroll
        for (int j = 0; j < TN; j++) acc[i][j] = 0.0f;

    for (int kt = 0; kt < K; kt += TBK) {
#pragma unroll
        for (int idx = tid; idx < TBM * TBK / 4; idx += THREADS) {
            int r = idx / (TBK / 4);
            int c = (idx % (TBK / 4)) * 4;
            int gr = rowBase + r;
            float4 v = make_float4(0.f, 0.f, 0.f, 0.f);
            if (gr < M) v = *(const float4*)(A + (size_t)gr * K + kt + c);
            As[c + 0][r] = v.x; As[c + 1][r] = v.y;
            As[c + 2][r] = v.z; As[c + 3][r] = v.w;
        }
#pragma unroll
        for (int idx = tid; idx < TBK * TBN / 4; idx += THREADS) {
            int r = idx / (TBN / 4);
            int c = (idx % (TBN / 4)) * 4;
            int gc = colBase + c;
            float4 v = make_float4(0.f, 0.f, 0.f, 0.f);
            if (gc < N) v = *(const float4*)(B + (size_t)(kt + r) * N + gc);
            *(float4*)&Bs[r][c] = v;
        }
        __syncthreads();
#pragma unroll
        for (int k = 0; k < TBK; k++) {
            float ra[TM], rb[TN];
#pragma unroll
            for (int i = 0; i < TM; i++) ra[i] = As[k][ty * TM + i];
#pragma unroll
            for (int j = 0; j < TN; j++) rb[j] = Bs[k][tx * TN + j];
#pragma unroll
            for (int i = 0; i < TM; i++)
#pragma unroll
                for (int j = 0; j < TN; j++)
                    acc[i][j] += ra[i] * rb[j];
        }
        __syncthreads();
    }

#pragma unroll
    for (int i = 0; i < TM; i++) {
        int gr = rowBase + ty * TM + i;
        if (gr >= M) continue;
        float d = dinv[gr];
#pragma unroll
        for (int j = 0; j < TN; j++) {
            int gc = colBase + tx * TN + j;
            if (gc < N) Q[(size_t)gr * N + gc] = acc[i][j] * d;
        }
    }
}

// ---------------- CSR aggregation layer 2 (fused bias+logsoftmax) -----------
__global__ void k_agg2(const float* __restrict__ b2,
                       float* __restrict__ out) {
    int node = blockIdx.x * (blockDim.x >> 5) + (threadIdx.x >> 5);
    int lane = threadIdx.x & 31;
    if (node >= N_NODES) return;
    int start = g_rowptr[node];
    int deg   = g_rowptr[node + 1] - start;

    float acc = g_q2[(size_t)node * CLS + lane];     // self term

    int myidx = (lane < deg) ? g_col[start + lane] : 0;
    int n32 = deg < 32 ? deg : 32;
    int e = 0;
    for (; e + 4 <= n32; e += 4) {
        int s0 = __shfl_sync(0xffffffffu, myidx, e);
        int s1 = __shfl_sync(0xffffffffu, myidx, e + 1);
        int s2 = __shfl_sync(0xffffffffu, myidx, e + 2);
        int s3 = __shfl_sync(0xffffffffu, myidx, e + 3);
        float v0 = g_q2[(size_t)s0 * CLS + lane];
        float v1 = g_q2[(size_t)s1 * CLS + lane];
        float v2 = g_q2[(size_t)s2 * CLS + lane];
        float v3 = g_q2[(size_t)s3 * CLS + lane];
        acc += (v0 + v1) + (v2 + v3);
    }
    for (; e < n32; e++) {
        int s = __shfl_sync(0xffffffffu, myidx, e);
        acc += g_q2[(size_t)s * CLS + lane];
    }
    for (e = 32; e < deg; e++)
        acc += g_q2[(size_t)g_col[start + e] * CLS + lane];

    float v = fmaf(acc, g_dinv[node], b2[lane]);
    float m = v;
#pragma unroll
    for (int o = 16; o > 0; o >>= 1) m = fmaxf(m, __shfl_xor_sync(0xffffffffu, m, o));
    float ex = __expf(v - m);
    float ssum = ex;
#pragma unroll
    for (int o = 16; o > 0; o >>= 1) ssum += __shfl_xor_sync(0xffffffffu, ssum, o);
    out[(size_t)node * CLS + lane] = v - m - __logf(ssum);
}

// ---------------- launch -----------------------------------------------------
extern "C" void kernel_launch(void* const* d_in, const int* in_sizes, int n_in,
                              void* d_out, int out_size) {
    const float* X   = (const float*)d_in[0];
    const int*   ei  = (const int*)d_in[1];
    const float* W1  = (const float*)d_in[2];
    const float* b1  = (const float*)d_in[3];
    const float* W2  = (const float*)d_in[4];
    const float* b2  = (const float*)d_in[5];
    float*       out = (float*)d_out;

    float *p_h1 = nullptr, *p_q2 = nullptr, *p_dinv = nullptr;
    cudaGetSymbolAddress((void**)&p_h1,   g_h1);
    cudaGetSymbolAddress((void**)&p_q2,   g_q2);
    cudaGetSymbolAddress((void**)&p_dinv, g_dinv);

    const int TB = 256;
    const int nodeGrid = (N_NODES + TB - 1) / TB;
    const int edgeGrid = (N_EDGES + TB - 1) / TB;

    // degree + CSR (+dinv fused into scan3)
    k_detect     <<<1, 32>>>(ei);
    k_zero_cnt   <<<nodeGrid, TB>>>();
    k_cnt_scatter<<<edgeGrid, TB>>>(ei);
    k_scan1      <<<N_SBLK, SCAN_B>>>();
    k_scan2      <<<1, 256>>>();
    k_scan3      <<<nodeGrid, TB>>>();
    k_fill       <<<edgeGrid, TB>>>(ei);

    // layer 1
    gemm1_mma<<<(N_NODES + BM - 1) / BM, 256>>>(X, W1);
    k_agg1   <<<(N_NODES * 32 + TB - 1) / TB, TB>>>(b1);

    // layer 2
    {
        dim3 grid(CLS / 32, (N_NODES + 127) / 128);
        sgemm2_kernel<128, 32, 32, 8, 2><<<grid, 256>>>(p_h1, W2, p_q2,
                                                        p_dinv, N_NODES, CLS, HID);
    }
    k_agg2<<<(N_NODES * 32 + TB - 1) / TB, TB>>>(b2, out);
}

// round 8
// speedup vs baseline: 1.5182x; 1.1437x over previous
#include <cuda_runtime.h>
#include <cuda_bf16.h>
#include <cstdint>

#define N_NODES 100000
#define N_EDGES 800000
#define F_IN    256
#define HID     128
#define CLS     32
#define SCAN_B  512
#define N_SBLK  ((N_NODES + SCAN_B - 1) / SCAN_B)   // 196

// ---------------- scratch (device globals: no allocation allowed) ----------
__device__ int   g_cnt[N_NODES];
__device__ float g_dinv[N_NODES];
__device__ int   g_rowptr[N_NODES + 1];
__device__ int   g_cursor[N_NODES];
__device__ int   g_col[N_EDGES];
__device__ int   g_bsum[N_SBLK];
__device__ int   g_boff[N_SBLK];
__device__ float g_q1 [(size_t)N_NODES * HID];
__device__ float g_h1 [(size_t)N_NODES * HID];
__device__ float g_q2 [(size_t)N_NODES * CLS];
__device__ int   g_is64;

// ---------------- stream/event for fork-join overlap (created at load) ------
static cudaStream_t g_s2 = nullptr;
static cudaEvent_t  g_e1 = nullptr, g_e2 = nullptr;
namespace {
struct HxStreamInit {
    HxStreamInit() {
        cudaStreamCreateWithFlags(&g_s2, cudaStreamNonBlocking);
        cudaEventCreateWithFlags(&g_e1, cudaEventDisableTiming);
        cudaEventCreateWithFlags(&g_e2, cudaEventDisableTiming);
    }
};
static HxStreamInit g_hx_stream_init;
}

// ---------------- helpers ----------------------------------------------------
__device__ __forceinline__ uint32_t smem_addr(const void* p) {
    return (uint32_t)__cvta_generic_to_shared(p);
}
#define LDSM_X4(r, a)                                                          \
    asm volatile("ldmatrix.sync.aligned.m8n8.x4.shared.b16 {%0,%1,%2,%3}, [%4];" \
                 : "=r"((r)[0]), "=r"((r)[1]), "=r"((r)[2]), "=r"((r)[3])      \
                 : "r"(a))
#define LDSM_X2T(r, a)                                                         \
    asm volatile("ldmatrix.sync.aligned.m8n8.x2.trans.shared.b16 {%0,%1}, [%2];" \
                 : "=r"((r)[0]), "=r"((r)[1]) : "r"(a))
#define MMA_BF16(c, a, b)                                                      \
    asm volatile("mma.sync.aligned.m16n8k16.row.col.f32.bf16.bf16.f32 "        \
                 "{%0,%1,%2,%3}, {%4,%5,%6,%7}, {%8,%9}, {%0,%1,%2,%3};"       \
                 : "+f"((c)[0]), "+f"((c)[1]), "+f"((c)[2]), "+f"((c)[3])      \
                 : "r"((a)[0]), "r"((a)[1]), "r"((a)[2]), "r"((a)[3]),         \
                   "r"((b)[0]), "r"((b)[1]))

__device__ __forceinline__ int edge_at(const int* __restrict__ ei,
                                       int which, int e, int is64) {
    size_t base = (size_t)which * N_EDGES + (size_t)e;
    return is64 ? ei[base * 2] : ei[base];
}

// ---------------- degree count (+ dtype probe fused) ------------------------
__global__ void k_zero_cnt(const int* __restrict__ ei) {
    int i = blockIdx.x * blockDim.x + threadIdx.x;
    if (i < N_NODES) g_cnt[i] = 0;
    if (i == 0) {
        int is64 = 1;
        for (int j = 0; j < 64; j++)
            if (ei[2 * j + 1] != 0) { is64 = 0; break; }
        g_is64 = is64;
    }
}
__global__ void k_cnt_scatter(const int* __restrict__ ei) {
    int e = blockIdx.x * blockDim.x + threadIdx.x;
    if (e >= N_EDGES) return;
    atomicAdd(&g_cnt[edge_at(ei, 1, e, g_is64)], 1);
}
__global__ void k_dinv() {
    int i = blockIdx.x * blockDim.x + threadIdx.x;
    if (i < N_NODES) g_dinv[i] = rsqrtf((float)(g_cnt[i] + 1));  // +1 self loop
}

// ---------------- CSR build: 3-phase scan + fill ----------------------------
__global__ void k_scan1() {
    __shared__ int sh[SCAN_B];
    int t = threadIdx.x;
    int i = blockIdx.x * SCAN_B + t;
    int v = (i < N_NODES) ? g_cnt[i] : 0;
    sh[t] = v;
    __syncthreads();
#pragma unroll
    for (int off = 1; off < SCAN_B; off <<= 1) {
        int x = (t >= off) ? sh[t - off] : 0;
        __syncthreads();
        sh[t] += x;
        __syncthreads();
    }
    if (i < N_NODES) g_rowptr[i] = sh[t] - v;
    if (t == SCAN_B - 1) g_bsum[blockIdx.x] = sh[t];
}
__global__ void k_scan2() {
    __shared__ int sh[256];
    int t = threadIdx.x;
    int v = (t < N_SBLK) ? g_bsum[t] : 0;
    sh[t] = v;
    __syncthreads();
#pragma unroll
    for (int off = 1; off < 256; off <<= 1) {
        int x = (t >= off) ? sh[t - off] : 0;
        __syncthreads();
        sh[t] += x;
        __syncthreads();
    }
    if (t < N_SBLK) g_boff[t] = sh[t] - v;
}
__global__ void k_scan3() {
    int i = blockIdx.x * blockDim.x + threadIdx.x;
    if (i < N_NODES) {
        int rp = g_rowptr[i] + g_boff[i / SCAN_B];
        g_rowptr[i] = rp;
        g_cursor[i] = rp;
    }
    if (i == 0) g_rowptr[N_NODES] = N_EDGES;
}
__global__ void k_fill(const int* __restrict__ ei) {
    int e = blockIdx.x * blockDim.x + threadIdx.x;
    if (e >= N_EDGES) return;
    int is64 = g_is64;
    int s = edge_at(ei, 0, e, is64);
    int d = edge_at(ei, 1, e, is64);
    int pos = atomicAdd(&g_cursor[d], 1);
    g_col[pos] = s;
}

// ---------------- layer-1 GEMM: mma.sync bf16-split (3xMMA) -----------------
// q1 = (X @ W1) * dinv[row]
#define BM 128
#define BN 128
#define BK 32
#define APAD 8
#define BPAD 8

__global__ __launch_bounds__(256, 1) void gemm1_mma(const float* __restrict__ X,
                                                    const float* __restrict__ W1) {
    __shared__ __align__(16) __nv_bfloat16 sAh[BM][BK + APAD];
    __shared__ __align__(16) __nv_bfloat16 sAl[BM][BK + APAD];
    __shared__ __align__(16) __nv_bfloat16 sBh[BK][BN + BPAD];
    __shared__ __align__(16) __nv_bfloat16 sBl[BK][BN + BPAD];

    const int tid  = threadIdx.x;
    const int lane = tid & 31;
    const int wid  = tid >> 5;
    const int wm   = wid >> 2;
    const int wn   = wid & 3;
    const int rowBase = blockIdx.x * BM;

    float acc[4][4][4];
#pragma unroll
    for (int mi = 0; mi < 4; mi++)
#pragma unroll
        for (int ni = 0; ni < 4; ni++)
#pragma unroll
            for (int r = 0; r < 4; r++) acc[mi][ni][r] = 0.f;

    for (int kt = 0; kt < F_IN; kt += BK) {
#pragma unroll
        for (int i = 0; i < 4; i++) {
            int idx = tid + i * 256;
            int r = idx >> 3, c4 = (idx & 7) * 4;
            int gr = rowBase + r;
            float4 v = make_float4(0.f, 0.f, 0.f, 0.f);
            if (gr < N_NODES)
                v = *(const float4*)(X + (size_t)gr * F_IN + kt + c4);
#pragma unroll
            for (int j = 0; j < 4; j++) {
                float x = (&v.x)[j];
                __nv_bfloat16 hi = __float2bfloat16(x);
                __nv_bfloat16 lo = __float2bfloat16(x - __bfloat162float(hi));
                sAh[r][c4 + j] = hi;
                sAl[r][c4 + j] = lo;
            }
        }
#pragma unroll
        for (int i = 0; i < 4; i++) {
            int idx = tid + i * 256;
            int k = idx >> 5, n4 = (idx & 31) * 4;
            float4 w = *(const float4*)(W1 + (size_t)(kt + k) * HID + n4);
#pragma unroll
            for (int j = 0; j < 4; j++) {
                float x = (&w.x)[j];
                __nv_bfloat16 hi = __float2bfloat16(x);
                __nv_bfloat16 lo = __float2bfloat16(x - __bfloat162float(hi));
                sBh[k][n4 + j] = hi;
                sBl[k][n4 + j] = lo;
            }
        }
        __syncthreads();

#pragma unroll
        for (int ks = 0; ks < BK / 16; ks++) {
            int k16 = ks * 16;
            uint32_t ah[4][4], al[4][4], bh[4][2], bl[4][2];
#pragma unroll
            for (int mi = 0; mi < 4; mi++) {
                int row = wm * 64 + mi * 16 + (lane & 15);
                int col = k16 + (lane >> 4) * 8;
                LDSM_X4(ah[mi], smem_addr(&sAh[row][col]));
                LDSM_X4(al[mi], smem_addr(&sAl[row][col]));
            }
#pragma unroll
            for (int ni = 0; ni < 4; ni++) {
                int krow = k16 + (lane & 15);
                int col  = wn * 32 + ni * 8;
                LDSM_X2T(bh[ni], smem_addr(&sBh[krow][col]));
                LDSM_X2T(bl[ni], smem_addr(&sBl[krow][col]));
            }
#pragma unroll
            for (int mi = 0; mi < 4; mi++)
#pragma unroll
                for (int ni = 0; ni < 4; ni++) {
                    MMA_BF16(acc[mi][ni], ah[mi], bh[ni]);
                    MMA_BF16(acc[mi][ni], ah[mi], bl[ni]);
                    MMA_BF16(acc[mi][ni], al[mi], bh[ni]);
                }
        }
        __syncthreads();
    }

    const int rBase = rowBase + wm * 64 + (lane >> 2);
    const int cBase = wn * 32 + (lane & 3) * 2;
#pragma unroll
    for (int mi = 0; mi < 4; mi++) {
        int gr0 = rBase + mi * 16;
        int gr1 = gr0 + 8;
        float d0 = (gr0 < N_NODES) ? g_dinv[gr0] : 0.f;
        float d1 = (gr1 < N_NODES) ? g_dinv[gr1] : 0.f;
#pragma unroll
        for (int ni = 0; ni < 4; ni++) {
            int gc = cBase + ni * 8;
            if (gr0 < N_NODES)
                *(float2*)(g_q1 + (size_t)gr0 * HID + gc) =
                    make_float2(acc[mi][ni][0] * d0, acc[mi][ni][1] * d0);
            if (gr1 < N_NODES)
                *(float2*)(g_q1 + (size_t)gr1 * HID + gc) =
                    make_float2(acc[mi][ni][2] * d1, acc[mi][ni][3] * d1);
        }
    }
}

// ---------------- CSR aggregation layer 1 (index-prefetch gather) -----------
__global__ void k_agg1(const float* __restrict__ b1) {
    int node = blockIdx.x * (blockDim.x >> 5) + (threadIdx.x >> 5);
    int lane = threadIdx.x & 31;
    if (node >= N_NODES) return;
    int start = g_rowptr[node];
    int deg   = g_rowptr[node + 1] - start;

    const float4* q1v = (const float4*)g_q1;
    float4 acc = q1v[(size_t)node * 32 + lane];      // self term

    int myidx = (lane < deg) ? g_col[start + lane] : 0;
    int n32 = deg < 32 ? deg : 32;
    int e = 0;
    for (; e + 4 <= n32; e += 4) {
        int s0 = __shfl_sync(0xffffffffu, myidx, e);
        int s1 = __shfl_sync(0xffffffffu, myidx, e + 1);
        int s2 = __shfl_sync(0xffffffffu, myidx, e + 2);
        int s3 = __shfl_sync(0xffffffffu, myidx, e + 3);
        float4 v0 = q1v[(size_t)s0 * 32 + lane];
        float4 v1 = q1v[(size_t)s1 * 32 + lane];
        float4 v2 = q1v[(size_t)s2 * 32 + lane];
        float4 v3 = q1v[(size_t)s3 * 32 + lane];
        acc.x += (v0.x + v1.x) + (v2.x + v3.x);
        acc.y += (v0.y + v1.y) + (v2.y + v3.y);
        acc.z += (v0.z + v1.z) + (v2.z + v3.z);
        acc.w += (v0.w + v1.w) + (v2.w + v3.w);
    }
    for (; e < n32; e++) {
        int s = __shfl_sync(0xffffffffu, myidx, e);
        float4 v = q1v[(size_t)s * 32 + lane];
        acc.x += v.x; acc.y += v.y; acc.z += v.z; acc.w += v.w;
    }
    for (e = 32; e < deg; e++) {
        int s = g_col[start + e];
        float4 v = q1v[(size_t)s * 32 + lane];
        acc.x += v.x; acc.y += v.y; acc.z += v.z; acc.w += v.w;
    }

    float d = g_dinv[node];
    float4 b = ((const float4*)b1)[lane];
    float4 o;
    o.x = fmaxf(fmaf(acc.x, d, b.x), 0.f);
    o.y = fmaxf(fmaf(acc.y, d, b.y), 0.f);
    o.z = fmaxf(fmaf(acc.z, d, b.z), 0.f);
    o.w = fmaxf(fmaf(acc.w, d, b.w), 0.f);
    ((float4*)(g_h1 + (size_t)node * HID))[lane] = o;
}

// ---------------- layer-2 GEMM: mma.sync bf16-split (3xMMA) -----------------
// q2 = (h1 @ W2) * dinv[row];  M tiles of 128, N=32, K=128
__global__ __launch_bounds__(256, 1) void gemm2_mma(const float* __restrict__ W2) {
    __shared__ __align__(16) __nv_bfloat16 sAh[128][BK + APAD];
    __shared__ __align__(16) __nv_bfloat16 sAl[128][BK + APAD];
    __shared__ __align__(16) __nv_bfloat16 sBh[BK][CLS + BPAD];
    __shared__ __align__(16) __nv_bfloat16 sBl[BK][CLS + BPAD];

    const int tid  = threadIdx.x;
    const int lane = tid & 31;
    const int wid  = tid >> 5;          // 0..7, warp handles rows wid*16..+16
    const int rowBase = blockIdx.x * 128;

    float acc[4][4];                    // [ni][reg], mi = 1 (16 rows/warp)
#pragma unroll
    for (int ni = 0; ni < 4; ni++)
#pragma unroll
        for (int r = 0; r < 4; r++) acc[ni][r] = 0.f;

    for (int kt = 0; kt < HID; kt += BK) {
        // A tile: h1[rowBase..+128, kt..+32) -> hi/lo
#pragma unroll
        for (int i = 0; i < 4; i++) {
            int idx = tid + i * 256;
            int r = idx >> 3, c4 = (idx & 7) * 4;
            int gr = rowBase + r;
            float4 v = make_float4(0.f, 0.f, 0.f, 0.f);
            if (gr < N_NODES)
                v = *(const float4*)(g_h1 + (size_t)gr * HID + kt + c4);
#pragma unroll
            for (int j = 0; j < 4; j++) {
                float x = (&v.x)[j];
                __nv_bfloat16 hi = __float2bfloat16(x);
                __nv_bfloat16 lo = __float2bfloat16(x - __bfloat162float(hi));
                sAh[r][c4 + j] = hi;
                sAl[r][c4 + j] = lo;
            }
        }
        // B tile: W2[kt..+32, 0..32) -> hi/lo (256 float4 slots, 1 per thread)
        {
            int k = tid >> 3, n4 = (tid & 7) * 4;
            float4 w = *(const float4*)(W2 + (size_t)(kt + k) * CLS + n4);
#pragma unroll
            for (int j = 0; j < 4; j++) {
                float x = (&w.x)[j];
                __nv_bfloat16 hi = __float2bfloat16(x);
                __nv_bfloat16 lo = __float2bfloat16(x - __bfloat162float(hi));
                sBh[k][n4 + j] = hi;
                sBl[k][n4 + j] = lo;
            }
        }
        __syncthreads();

#pragma unroll
        for (int ks = 0; ks < BK / 16; ks++) {
            int k16 = ks * 16;
            uint32_t ah[4], al[4], bh[4][2], bl[4][2];
            {
                int row = wid * 16 + (lane & 15);
                int col = k16 + (lane >> 4) * 8;
                LDSM_X4(ah, smem_addr(&sAh[row][col]));
                LDSM_X4(al, smem_addr(&sAl[row][col]));
            }
#pragma unroll
            for (int ni = 0; ni < 4; ni++) {
                int krow = k16 + (lane & 15);
                int col  = ni * 8;
                LDSM_X2T(bh[ni], smem_addr(&sBh[krow][col]));
                LDSM_X2T(bl[ni], smem_addr(&sBl[krow][col]));
            }
#pragma unroll
            for (int ni = 0; ni < 4; ni++) {
                MMA_BF16(acc[ni], ah, bh[ni]);
                MMA_BF16(acc[ni], ah, bl[ni]);
                MMA_BF16(acc[ni], al, bh[ni]);
            }
        }
        __syncthreads();
    }

    const int r0 = rowBase + wid * 16 + (lane >> 2);
    const int r1 = r0 + 8;
    const int cBase = (lane & 3) * 2;
    float d0 = (r0 < N_NODES) ? g_dinv[r0] : 0.f;
    float d1 = (r1 < N_NODES) ? g_dinv[r1] : 0.f;
#pragma unroll
    for (int ni = 0; ni < 4; ni++) {
        int gc = cBase + ni * 8;
        if (r0 < N_NODES)
            *(float2*)(g_q2 + (size_t)r0 * CLS + gc) =
                make_float2(acc[ni][0] * d0, acc[ni][1] * d0);
        if (r1 < N_NODES)
            *(float2*)(g_q2 + (size_t)r1 * CLS + gc) =
                make_float2(acc[ni][2] * d1, acc[ni][3] * d1);
    }
}

// ---------------- CSR aggregation layer 2 (fused bias+logsoftmax) -----------
__global__ void k_agg2(const float* __restrict__ b2,
                       float* __restrict__ out) {
    int node = blockIdx.x * (blockDim.x >> 5) + (threadIdx.x >> 5);
    int lane = threadIdx.x & 31;
    if (node >= N_NODES) return;
    int start = g_rowptr[node];
    int deg   = g_rowptr[node + 1] - start;

    float acc = g_q2[(size_t)node * CLS + lane];     // self term

    int myidx = (lane < deg) ? g_col[start + lane] : 0;
    int n32 = deg < 32 ? deg : 32;
    int e = 0;
    for (; e + 4 <= n32; e += 4) {
        int s0 = __shfl_sync(0xffffffffu, myidx, e);
        int s1 = __shfl_sync(0xffffffffu, myidx, e + 1);
        int s2 = __shfl_sync(0xffffffffu, myidx, e + 2);
        int s3 = __shfl_sync(0xffffffffu, myidx, e + 3);
        float v0 = g_q2[(size_t)s0 * CLS + lane];
        float v1 = g_q2[(size_t)s1 * CLS + lane];
        float v2 = g_q2[(size_t)s2 * CLS + lane];
        float v3 = g_q2[(size_t)s3 * CLS + lane];
        acc += (v0 + v1) + (v2 + v3);
    }
    for (; e < n32; e++) {
        int s = __shfl_sync(0xffffffffu, myidx, e);
        acc += g_q2[(size_t)s * CLS + lane];
    }
    for (e = 32; e < deg; e++)
        acc += g_q2[(size_t)g_col[start + e] * CLS + lane];

    float v = fmaf(acc, g_dinv[node], b2[lane]);
    float m = v;
#pragma unroll
    for (int o = 16; o > 0; o >>= 1) m = fmaxf(m, __shfl_xor_sync(0xffffffffu, m, o));
    float ex = __expf(v - m);
    float ssum = ex;
#pragma unroll
    for (int o = 16; o > 0; o >>= 1) ssum += __shfl_xor_sync(0xffffffffu, ssum, o);
    out[(size_t)node * CLS + lane] = v - m - __logf(ssum);
}

// ---------------- launch -----------------------------------------------------
extern "C" void kernel_launch(void* const* d_in, const int* in_sizes, int n_in,
                              void* d_out, int out_size) {
    const float* X   = (const float*)d_in[0];
    const int*   ei  = (const int*)d_in[1];
    const float* W1  = (const float*)d_in[2];
    const float* b1  = (const float*)d_in[3];
    const float* W2  = (const float*)d_in[4];
    const float* b2  = (const float*)d_in[5];
    float*       out = (float*)d_out;

    const int TB = 256;
    const int nodeGrid = (N_NODES + TB - 1) / TB;
    const int edgeGrid = (N_EDGES + TB - 1) / TB;
    const bool fork = (g_s2 != nullptr) && (g_e1 != nullptr) && (g_e2 != nullptr);

    // degree + dinv (dinv only needs counts — computed before the fork)
    k_zero_cnt   <<<nodeGrid, TB>>>(ei);
    k_cnt_scatter<<<edgeGrid, TB>>>(ei);
    k_dinv       <<<nodeGrid, TB>>>();

    // fork: GEMM1 on side stream, CSR scan/fill on main stream (independent)
    if (fork) {
        cudaEventRecord(g_e1, 0);
        cudaStreamWaitEvent(g_s2, g_e1, 0);
        gemm1_mma<<<(N_NODES + BM - 1) / BM, 256, 0, g_s2>>>(X, W1);
        cudaEventRecord(g_e2, g_s2);
    } else {
        gemm1_mma<<<(N_NODES + BM - 1) / BM, 256>>>(X, W1);
    }

    k_scan1<<<N_SBLK, SCAN_B>>>();
    k_scan2<<<1, 256>>>();
    k_scan3<<<nodeGrid, TB>>>();
    k_fill <<<edgeGrid, TB>>>(ei);

    if (fork) cudaStreamWaitEvent(0, g_e2, 0);   // join before agg1

    // layer 1 aggregation, layer 2 GEMM + aggregation
    k_agg1   <<<(N_NODES * 32 + TB - 1) / TB, TB>>>(b1);
    gemm2_mma<<<(N_NODES + 127) / 128, 256>>>(W2);
    k_agg2   <<<(N_NODES * 32 + TB - 1) / TB, TB>>>(b2, out);
}

// round 9
// speedup vs baseline: 1.5931x; 1.0493x over previous
#include <cuda_runtime.h>
#include <cuda_bf16.h>
#include <cstdint>

#define N_NODES 100000
#define N_EDGES 800000
#define F_IN    256
#define HID     128
#define CLS     32
#define SCAN_B  512
#define N_SBLK  ((N_NODES + SCAN_B - 1) / SCAN_B)   // 196

// ---------------- scratch (device globals: no allocation allowed) ----------
__device__ int   g_cnt[N_NODES];
__device__ float g_dinv[N_NODES];
__device__ int   g_rowptr[N_NODES + 1];
__device__ int   g_cursor[N_NODES];
__device__ int   g_col[N_EDGES];
__device__ int   g_bsum[N_SBLK];
__device__ int   g_boff[N_SBLK];
__device__ float g_q1 [(size_t)N_NODES * HID];
__device__ float g_h1 [(size_t)N_NODES * HID];
__device__ float g_q2 [(size_t)N_NODES * CLS];
__device__ int   g_is64;

// ---------------- stream/event for fork-join overlap (created at load) ------
static cudaStream_t g_s2 = nullptr;
static cudaEvent_t  g_e1 = nullptr, g_e2 = nullptr;
namespace {
struct HxStreamInit {
    HxStreamInit() {
        cudaStreamCreateWithFlags(&g_s2, cudaStreamNonBlocking);
        cudaEventCreateWithFlags(&g_e1, cudaEventDisableTiming);
        cudaEventCreateWithFlags(&g_e2, cudaEventDisableTiming);
    }
};
static HxStreamInit g_hx_stream_init;
}

// ---------------- helpers ----------------------------------------------------
__device__ __forceinline__ uint32_t smem_addr(const void* p) {
    return (uint32_t)__cvta_generic_to_shared(p);
}
#define LDSM_X4(r, a)                                                          \
    asm volatile("ldmatrix.sync.aligned.m8n8.x4.shared.b16 {%0,%1,%2,%3}, [%4];" \
                 : "=r"((r)[0]), "=r"((r)[1]), "=r"((r)[2]), "=r"((r)[3])      \
                 : "r"(a))
#define LDSM_X2T(r, a)                                                         \
    asm volatile("ldmatrix.sync.aligned.m8n8.x2.trans.shared.b16 {%0,%1}, [%2];" \
                 : "=r"((r)[0]), "=r"((r)[1]) : "r"(a))
#define MMA_BF16(c, a, b)                                                      \
    asm volatile("mma.sync.aligned.m16n8k16.row.col.f32.bf16.bf16.f32 "        \
                 "{%0,%1,%2,%3}, {%4,%5,%6,%7}, {%8,%9}, {%0,%1,%2,%3};"       \
                 : "+f"((c)[0]), "+f"((c)[1]), "+f"((c)[2]), "+f"((c)[3])      \
                 : "r"((a)[0]), "r"((a)[1]), "r"((a)[2]), "r"((a)[3]),         \
                   "r"((b)[0]), "r"((b)[1]))

__device__ __forceinline__ int edge_at(const int* __restrict__ ei,
                                       int which, int e, int is64) {
    size_t base = (size_t)which * N_EDGES + (size_t)e;
    return is64 ? ei[base * 2] : ei[base];
}

// ---------------- degree count (+ dtype probe fused) ------------------------
__global__ void k_zero_cnt(const int* __restrict__ ei) {
    int i = blockIdx.x * blockDim.x + threadIdx.x;
    if (i < N_NODES) g_cnt[i] = 0;
    if (i == 0) {
        int is64 = 1;
        for (int j = 0; j < 64; j++)
            if (ei[2 * j + 1] != 0) { is64 = 0; break; }
        g_is64 = is64;
    }
}
__global__ void k_cnt_scatter(const int* __restrict__ ei) {
    int e = blockIdx.x * blockDim.x + threadIdx.x;
    if (e >= N_EDGES) return;
    atomicAdd(&g_cnt[edge_at(ei, 1, e, g_is64)], 1);
}
__global__ void k_dinv() {
    int i = blockIdx.x * blockDim.x + threadIdx.x;
    if (i < N_NODES) g_dinv[i] = rsqrtf((float)(g_cnt[i] + 1));  // +1 self loop
}

// ---------------- CSR build: 3-phase scan + fill ----------------------------
__global__ void k_scan1() {
    __shared__ int sh[SCAN_B];
    int t = threadIdx.x;
    int i = blockIdx.x * SCAN_B + t;
    int v = (i < N_NODES) ? g_cnt[i] : 0;
    sh[t] = v;
    __syncthreads();
#pragma unroll
    for (int off = 1; off < SCAN_B; off <<= 1) {
        int x = (t >= off) ? sh[t - off] : 0;
        __syncthreads();
        sh[t] += x;
        __syncthreads();
    }
    if (i < N_NODES) g_rowptr[i] = sh[t] - v;
    if (t == SCAN_B - 1) g_bsum[blockIdx.x] = sh[t];
}
__global__ void k_scan2() {
    __shared__ int sh[256];
    int t = threadIdx.x;
    int v = (t < N_SBLK) ? g_bsum[t] : 0;
    sh[t] = v;
    __syncthreads();
#pragma unroll
    for (int off = 1; off < 256; off <<= 1) {
        int x = (t >= off) ? sh[t - off] : 0;
        __syncthreads();
        sh[t] += x;
        __syncthreads();
    }
    if (t < N_SBLK) g_boff[t] = sh[t] - v;
}
__global__ void k_scan3() {
    int i = blockIdx.x * blockDim.x + threadIdx.x;
    if (i < N_NODES) {
        int rp = g_rowptr[i] + g_boff[i / SCAN_B];
        g_rowptr[i] = rp;
        g_cursor[i] = rp;
    }
    if (i == 0) g_rowptr[N_NODES] = N_EDGES;
}
__global__ void k_fill(const int* __restrict__ ei) {
    int e = blockIdx.x * blockDim.x + threadIdx.x;
    if (e >= N_EDGES) return;
    int is64 = g_is64;
    int s = edge_at(ei, 0, e, is64);
    int d = edge_at(ei, 1, e, is64);
    int pos = atomicAdd(&g_cursor[d], 1);
    g_col[pos] = s;
}

// ---------------- layer-1 GEMM: mma.sync bf16-split (3xMMA) -----------------
// q1 = (X @ W1) * dinv[row].  BM=64 for 2 CTAs/SM occupancy.
#define BM 64
#define BN 128
#define BK 32
#define APAD 8
#define BPAD 8

__global__ __launch_bounds__(256, 2) void gemm1_mma(const float* __restrict__ X,
                                                    const float* __restrict__ W1) {
    __shared__ __align__(16) __nv_bfloat16 sAh[BM][BK + APAD];
    __shared__ __align__(16) __nv_bfloat16 sAl[BM][BK + APAD];
    __shared__ __align__(16) __nv_bfloat16 sBh[BK][BN + BPAD];
    __shared__ __align__(16) __nv_bfloat16 sBl[BK][BN + BPAD];

    const int tid  = threadIdx.x;
    const int lane = tid & 31;
    const int wid  = tid >> 5;
    const int wm   = wid >> 2;       // 0..1  (32 rows each)
    const int wn   = wid & 3;        // 0..3  (32 cols each)
    const int rowBase = blockIdx.x * BM;

    float acc[2][4][4];
#pragma unroll
    for (int mi = 0; mi < 2; mi++)
#pragma unroll
        for (int ni = 0; ni < 4; ni++)
#pragma unroll
            for (int r = 0; r < 4; r++) acc[mi][ni][r] = 0.f;

    for (int kt = 0; kt < F_IN; kt += BK) {
        // ---- A tile: X[rowBase..+64, kt..+32) -> bf16 hi/lo (512 float4) ----
#pragma unroll
        for (int i = 0; i < 2; i++) {
            int idx = tid + i * 256;
            int r = idx >> 3, c4 = (idx & 7) * 4;
            int gr = rowBase + r;
            float4 v = make_float4(0.f, 0.f, 0.f, 0.f);
            if (gr < N_NODES)
                v = *(const float4*)(X + (size_t)gr * F_IN + kt + c4);
#pragma unroll
            for (int j = 0; j < 4; j++) {
                float x = (&v.x)[j];
                __nv_bfloat16 hi = __float2bfloat16(x);
                __nv_bfloat16 lo = __float2bfloat16(x - __bfloat162float(hi));
                sAh[r][c4 + j] = hi;
                sAl[r][c4 + j] = lo;
            }
        }
        // ---- B tile: W1[kt..+32, 0..128) -> bf16 hi/lo (1024 float4) ----
#pragma unroll
        for (int i = 0; i < 4; i++) {
            int idx = tid + i * 256;
            int k = idx >> 5, n4 = (idx & 31) * 4;
            float4 w = *(const float4*)(W1 + (size_t)(kt + k) * HID + n4);
#pragma unroll
            for (int j = 0; j < 4; j++) {
                float x = (&w.x)[j];
                __nv_bfloat16 hi = __float2bfloat16(x);
                __nv_bfloat16 lo = __float2bfloat16(x - __bfloat162float(hi));
                sBh[k][n4 + j] = hi;
                sBl[k][n4 + j] = lo;
            }
        }
        __syncthreads();

#pragma unroll
        for (int ks = 0; ks < BK / 16; ks++) {
            int k16 = ks * 16;
            uint32_t ah[2][4], al[2][4], bh[4][2], bl[4][2];
#pragma unroll
            for (int mi = 0; mi < 2; mi++) {
                int row = wm * 32 + mi * 16 + (lane & 15);
                int col = k16 + (lane >> 4) * 8;
                LDSM_X4(ah[mi], smem_addr(&sAh[row][col]));
                LDSM_X4(al[mi], smem_addr(&sAl[row][col]));
            }
#pragma unroll
            for (int ni = 0; ni < 4; ni++) {
                int krow = k16 + (lane & 15);
                int col  = wn * 32 + ni * 8;
                LDSM_X2T(bh[ni], smem_addr(&sBh[krow][col]));
                LDSM_X2T(bl[ni], smem_addr(&sBl[krow][col]));
            }
#pragma unroll
            for (int mi = 0; mi < 2; mi++)
#pragma unroll
                for (int ni = 0; ni < 4; ni++) {
                    MMA_BF16(acc[mi][ni], ah[mi], bh[ni]);
                    MMA_BF16(acc[mi][ni], ah[mi], bl[ni]);
                    MMA_BF16(acc[mi][ni], al[mi], bh[ni]);
                }
        }
        __syncthreads();
    }

    const int rBase = rowBase + wm * 32 + (lane >> 2);
    const int cBase = wn * 32 + (lane & 3) * 2;
#pragma unroll
    for (int mi = 0; mi < 2; mi++) {
        int gr0 = rBase + mi * 16;
        int gr1 = gr0 + 8;
        float d0 = (gr0 < N_NODES) ? g_dinv[gr0] : 0.f;
        float d1 = (gr1 < N_NODES) ? g_dinv[gr1] : 0.f;
#pragma unroll
        for (int ni = 0; ni < 4; ni++) {
            int gc = cBase + ni * 8;
            if (gr0 < N_NODES)
                *(float2*)(g_q1 + (size_t)gr0 * HID + gc) =
                    make_float2(acc[mi][ni][0] * d0, acc[mi][ni][1] * d0);
            if (gr1 < N_NODES)
                *(float2*)(g_q1 + (size_t)gr1 * HID + gc) =
                    make_float2(acc[mi][ni][2] * d1, acc[mi][ni][3] * d1);
        }
    }
}

// ---------------- CSR aggregation layer 1 (index-prefetch gather) -----------
__global__ void k_agg1(const float* __restrict__ b1) {
    int node = blockIdx.x * (blockDim.x >> 5) + (threadIdx.x >> 5);
    int lane = threadIdx.x & 31;
    if (node >= N_NODES) return;
    int start = g_rowptr[node];
    int deg   = g_rowptr[node + 1] - start;

    const float4* q1v = (const float4*)g_q1;
    float4 acc = q1v[(size_t)node * 32 + lane];      // self term

    int myidx = (lane < deg) ? g_col[start + lane] : 0;
    int n32 = deg < 32 ? deg : 32;
    int e = 0;
    for (; e + 4 <= n32; e += 4) {
        int s0 = __shfl_sync(0xffffffffu, myidx, e);
        int s1 = __shfl_sync(0xffffffffu, myidx, e + 1);
        int s2 = __shfl_sync(0xffffffffu, myidx, e + 2);
        int s3 = __shfl_sync(0xffffffffu, myidx, e + 3);
        float4 v0 = q1v[(size_t)s0 * 32 + lane];
        float4 v1 = q1v[(size_t)s1 * 32 + lane];
        float4 v2 = q1v[(size_t)s2 * 32 + lane];
        float4 v3 = q1v[(size_t)s3 * 32 + lane];
        acc.x += (v0.x + v1.x) + (v2.x + v3.x);
        acc.y += (v0.y + v1.y) + (v2.y + v3.y);
        acc.z += (v0.z + v1.z) + (v2.z + v3.z);
        acc.w += (v0.w + v1.w) + (v2.w + v3.w);
    }
    for (; e < n32; e++) {
        int s = __shfl_sync(0xffffffffu, myidx, e);
        float4 v = q1v[(size_t)s * 32 + lane];
        acc.x += v.x; acc.y += v.y; acc.z += v.z; acc.w += v.w;
    }
    for (e = 32; e < deg; e++) {
        int s = g_col[start + e];
        float4 v = q1v[(size_t)s * 32 + lane];
        acc.x += v.x; acc.y += v.y; acc.z += v.z; acc.w += v.w;
    }

    float d = g_dinv[node];
    float4 b = ((const float4*)b1)[lane];
    float4 o;
    o.x = fmaxf(fmaf(acc.x, d, b.x), 0.f);
    o.y = fmaxf(fmaf(acc.y, d, b.y), 0.f);
    o.z = fmaxf(fmaf(acc.z, d, b.z), 0.f);
    o.w = fmaxf(fmaf(acc.w, d, b.w), 0.f);
    ((float4*)(g_h1 + (size_t)node * HID))[lane] = o;
}

// ---------------- layer-2 GEMM: mma.sync bf16-split (3xMMA) -----------------
// q2 = (h1 @ W2) * dinv[row];  M tiles of 128, N=32, K=128
__global__ __launch_bounds__(256, 2) void gemm2_mma(const float* __restrict__ W2) {
    __shared__ __align__(16) __nv_bfloat16 sAh[128][BK + APAD];
    __shared__ __align__(16) __nv_bfloat16 sAl[128][BK + APAD];
    __shared__ __align__(16) __nv_bfloat16 sBh[BK][CLS + BPAD];
    __shared__ __align__(16) __nv_bfloat16 sBl[BK][CLS + BPAD];

    const int tid  = threadIdx.x;
    const int lane = tid & 31;
    const int wid  = tid >> 5;          // 0..7, warp handles rows wid*16..+16
    const int rowBase = blockIdx.x * 128;

    float acc[4][4];
#pragma unroll
    for (int ni = 0; ni < 4; ni++)
#pragma unroll
        for (int r = 0; r < 4; r++) acc[ni][r] = 0.f;

    for (int kt = 0; kt < HID; kt += BK) {
#pragma unroll
        for (int i = 0; i < 4; i++) {
            int idx = tid + i * 256;
            int r = idx >> 3, c4 = (idx & 7) * 4;
            int gr = rowBase + r;
            float4 v = make_float4(0.f, 0.f, 0.f, 0.f);
            if (gr < N_NODES)
                v = *(const float4*)(g_h1 + (size_t)gr * HID + kt + c4);
#pragma unroll
            for (int j = 0; j < 4; j++) {
                float x = (&v.x)[j];
                __nv_bfloat16 hi = __float2bfloat16(x);
                __nv_bfloat16 lo = __float2bfloat16(x - __bfloat162float(hi));
                sAh[r][c4 + j] = hi;
                sAl[r][c4 + j] = lo;
            }
        }
        {
            int k = tid >> 3, n4 = (tid & 7) * 4;
            float4 w = *(const float4*)(W2 + (size_t)(kt + k) * CLS + n4);
#pragma unroll
            for (int j = 0; j < 4; j++) {
                float x = (&w.x)[j];
                __nv_bfloat16 hi = __float2bfloat16(x);
                __nv_bfloat16 lo = __float2bfloat16(x - __bfloat162float(hi));
                sBh[k][n4 + j] = hi;
                sBl[k][n4 + j] = lo;
            }
        }
        __syncthreads();

#pragma unroll
        for (int ks = 0; ks < BK / 16; ks++) {
            int k16 = ks * 16;
            uint32_t ah[4], al[4], bh[4][2], bl[4][2];
            {
                int row = wid * 16 + (lane & 15);
                int col = k16 + (lane >> 4) * 8;
                LDSM_X4(ah, smem_addr(&sAh[row][col]));
                LDSM_X4(al, smem_addr(&sAl[row][col]));
            }
#pragma unroll
            for (int ni = 0; ni < 4; ni++) {
                int krow = k16 + (lane & 15);
                int col  = ni * 8;
                LDSM_X2T(bh[ni], smem_addr(&sBh[krow][col]));
                LDSM_X2T(bl[ni], smem_addr(&sBl[krow][col]));
            }
#pragma unroll
            for (int ni = 0; ni < 4; ni++) {
                MMA_BF16(acc[ni], ah, bh[ni]);
                MMA_BF16(acc[ni], ah, bl[ni]);
                MMA_BF16(acc[ni], al, bh[ni]);
            }
        }
        __syncthreads();
    }

    const int r0 = rowBase + wid * 16 + (lane >> 2);
    const int r1 = r0 + 8;
    const int cBase = (lane & 3) * 2;
    float d0 = (r0 < N_NODES) ? g_dinv[r0] : 0.f;
    float d1 = (r1 < N_NODES) ? g_dinv[r1] : 0.f;
#pragma unroll
    for (int ni = 0; ni < 4; ni++) {
        int gc = cBase + ni * 8;
        if (r0 < N_NODES)
            *(float2*)(g_q2 + (size_t)r0 * CLS + gc) =
                make_float2(acc[ni][0] * d0, acc[ni][1] * d0);
        if (r1 < N_NODES)
            *(float2*)(g_q2 + (size_t)r1 * CLS + gc) =
                make_float2(acc[ni][2] * d1, acc[ni][3] * d1);
    }
}

// ---------------- CSR aggregation layer 2 (fused bias+logsoftmax) -----------
__global__ void k_agg2(const float* __restrict__ b2,
                       float* __restrict__ out) {
    int node = blockIdx.x * (blockDim.x >> 5) + (threadIdx.x >> 5);
    int lane = threadIdx.x & 31;
    if (node >= N_NODES) return;
    int start = g_rowptr[node];
    int deg   = g_rowptr[node + 1] - start;

    float acc = g_q2[(size_t)node * CLS + lane];     // self term

    int myidx = (lane < deg) ? g_col[start + lane] : 0;
    int n32 = deg < 32 ? deg : 32;
    int e = 0;
    for (; e + 4 <= n32; e += 4) {
        int s0 = __shfl_sync(0xffffffffu, myidx, e);
        int s1 = __shfl_sync(0xffffffffu, myidx, e + 1);
        int s2 = __shfl_sync(0xffffffffu, myidx, e + 2);
        int s3 = __shfl_sync(0xffffffffu, myidx, e + 3);
        float v0 = g_q2[(size_t)s0 * CLS + lane];
        float v1 = g_q2[(size_t)s1 * CLS + lane];
        float v2 = g_q2[(size_t)s2 * CLS + lane];
        float v3 = g_q2[(size_t)s3 * CLS + lane];
        acc += (v0 + v1) + (v2 + v3);
    }
    for (; e < n32; e++) {
        int s = __shfl_sync(0xffffffffu, myidx, e);
        acc += g_q2[(size_t)s * CLS + lane];
    }
    for (e = 32; e < deg; e++)
        acc += g_q2[(size_t)g_col[start + e] * CLS + lane];

    float v = fmaf(acc, g_dinv[node], b2[lane]);
    float m = v;
#pragma unroll
    for (int o = 16; o > 0; o >>= 1) m = fmaxf(m, __shfl_xor_sync(0xffffffffu, m, o));
    float ex = __expf(v - m);
    float ssum = ex;
#pragma unroll
    for (int o = 16; o > 0; o >>= 1) ssum += __shfl_xor_sync(0xffffffffu, ssum, o);
    out[(size_t)node * CLS + lane] = v - m - __logf(ssum);
}

// ---------------- launch -----------------------------------------------------
extern "C" void kernel_launch(void* const* d_in, const int* in_sizes, int n_in,
                              void* d_out, int out_size) {
    const float* X   = (const float*)d_in[0];
    const int*   ei  = (const int*)d_in[1];
    const float* W1  = (const float*)d_in[2];
    const float* b1  = (const float*)d_in[3];
    const float* W2  = (const float*)d_in[4];
    const float* b2  = (const float*)d_in[5];
    float*       out = (float*)d_out;

    const int TB = 256;
    const int nodeGrid = (N_NODES + TB - 1) / TB;
    const int edgeGrid = (N_EDGES + TB - 1) / TB;
    const bool fork = (g_s2 != nullptr) && (g_e1 != nullptr) && (g_e2 != nullptr);

    // degree + dinv (dinv only needs counts — computed before the fork)
    k_zero_cnt   <<<nodeGrid, TB>>>(ei);
    k_cnt_scatter<<<edgeGrid, TB>>>(ei);
    k_dinv       <<<nodeGrid, TB>>>();

    // fork: GEMM1 on side stream, CSR scan/fill on main stream (independent)
    if (fork) {
        cudaEventRecord(g_e1, 0);
        cudaStreamWaitEvent(g_s2, g_e1, 0);
        gemm1_mma<<<(N_NODES + BM - 1) / BM, 256, 0, g_s2>>>(X, W1);
        cudaEventRecord(g_e2, g_s2);
    } else {
        gemm1_mma<<<(N_NODES + BM - 1) / BM, 256>>>(X, W1);
    }

    k_scan1<<<N_SBLK, SCAN_B>>>();
    k_scan2<<<1, 256>>>();
    k_scan3<<<nodeGrid, TB>>>();
    k_fill <<<edgeGrid, TB>>>(ei);

    if (fork) cudaStreamWaitEvent(0, g_e2, 0);   // join before agg1

    // layer 1 aggregation, layer 2 GEMM + aggregation
    k_agg1   <<<(N_NODES * 32 + TB - 1) / TB, TB>>>(b1);
    gemm2_mma<<<(N_NODES + 127) / 128, 256>>>(W2);
    k_agg2   <<<(N_NODES * 32 + TB - 1) / TB, TB>>>(b2, out);
}

// round 10
// speedup vs baseline: 1.8170x; 1.1406x over previous
#include <cuda_runtime.h>
#include <cuda_bf16.h>
#include <cstdint>

#define N_NODES 100000
#define N_EDGES 800000
#define F_IN    256
#define HID     128
#define CLS     32
#define SCAN_B  512
#define N_SBLK  ((N_NODES + SCAN_B - 1) / SCAN_B)   // 196

// ---------------- scratch (device globals: no allocation allowed) ----------
__device__ int   g_cnt[N_NODES];
__device__ float g_dinv[N_NODES];
__device__ int   g_rowptr[N_NODES + 1];
__device__ int   g_cursor[N_NODES];
__device__ int   g_col[N_EDGES];
__device__ int   g_bsum[N_SBLK];
__device__ int   g_boff[N_SBLK];
__device__ float g_q1 [(size_t)N_NODES * HID];
__device__ float g_h1 [(size_t)N_NODES * HID];
__device__ float g_q2 [(size_t)N_NODES * CLS];
__device__ __nv_bfloat16 g_w1h[F_IN * HID];
__device__ __nv_bfloat16 g_w1l[F_IN * HID];
__device__ __nv_bfloat16 g_w2h[HID * CLS];
__device__ __nv_bfloat16 g_w2l[HID * CLS];
__device__ int   g_is64;

// ---------------- stream/events for fork-join overlap (created at load) -----
static cudaStream_t g_s2 = nullptr;
static cudaEvent_t  g_e0 = nullptr, g_e1 = nullptr, g_e2 = nullptr;
namespace {
struct HxStreamInit {
    HxStreamInit() {
        cudaStreamCreateWithFlags(&g_s2, cudaStreamNonBlocking);
        cudaEventCreateWithFlags(&g_e0, cudaEventDisableTiming);
        cudaEventCreateWithFlags(&g_e1, cudaEventDisableTiming);
        cudaEventCreateWithFlags(&g_e2, cudaEventDisableTiming);
    }
};
static HxStreamInit g_hx_stream_init;
}

// ---------------- helpers ----------------------------------------------------
__device__ __forceinline__ uint32_t smem_addr(const void* p) {
    return (uint32_t)__cvta_generic_to_shared(p);
}
#define LDSM_X4(r, a)                                                          \
    asm volatile("ldmatrix.sync.aligned.m8n8.x4.shared.b16 {%0,%1,%2,%3}, [%4];" \
                 : "=r"((r)[0]), "=r"((r)[1]), "=r"((r)[2]), "=r"((r)[3])      \
                 : "r"(a))
#define LDSM_X2T(r, a)                                                         \
    asm volatile("ldmatrix.sync.aligned.m8n8.x2.trans.shared.b16 {%0,%1}, [%2];" \
                 : "=r"((r)[0]), "=r"((r)[1]) : "r"(a))
#define MMA_BF16(c, a, b)                                                      \
    asm volatile("mma.sync.aligned.m16n8k16.row.col.f32.bf16.bf16.f32 "        \
                 "{%0,%1,%2,%3}, {%4,%5,%6,%7}, {%8,%9}, {%0,%1,%2,%3};"       \
                 : "+f"((c)[0]), "+f"((c)[1]), "+f"((c)[2]), "+f"((c)[3])      \
                 : "r"((a)[0]), "r"((a)[1]), "r"((a)[2]), "r"((a)[3]),         \
                   "r"((b)[0]), "r"((b)[1]))

__device__ __forceinline__ int edge_at(const int* __restrict__ ei,
                                       int which, int e, int is64) {
    size_t base = (size_t)which * N_EDGES + (size_t)e;
    return is64 ? ei[base * 2] : ei[base];
}
__device__ __forceinline__ uint32_t pack_bf2(float a, float b) {
    __nv_bfloat162 p = make_bfloat162(__float2bfloat16(a), __float2bfloat16(b));
    return *(uint32_t*)&p;
}

// ---------------- weight conversion (hi/lo bf16 split) ----------------------
__global__ void k_convw(const float* __restrict__ W1,
                        const float* __restrict__ W2) {
    int i = blockIdx.x * blockDim.x + threadIdx.x;
    if (i < F_IN * HID) {
        float x = W1[i];
        __nv_bfloat16 h = __float2bfloat16(x);
        g_w1h[i] = h;
        g_w1l[i] = __float2bfloat16(x - __bfloat162float(h));
    }
    if (i < HID * CLS) {
        float x = W2[i];
        __nv_bfloat16 h = __float2bfloat16(x);
        g_w2h[i] = h;
        g_w2l[i] = __float2bfloat16(x - __bfloat162float(h));
    }
}

// ---------------- degree count (+ dtype probe fused) ------------------------
__global__ void k_zero_cnt(const int* __restrict__ ei) {
    int i = blockIdx.x * blockDim.x + threadIdx.x;
    if (i < N_NODES) g_cnt[i] = 0;
    if (i == 0) {
        int is64 = 1;
        for (int j = 0; j < 64; j++)
            if (ei[2 * j + 1] != 0) { is64 = 0; break; }
        g_is64 = is64;
    }
}
__global__ void k_cnt_scatter(const int* __restrict__ ei) {
    int e = blockIdx.x * blockDim.x + threadIdx.x;
    if (e >= N_EDGES) return;
    atomicAdd(&g_cnt[edge_at(ei, 1, e, g_is64)], 1);
}
__global__ void k_dinv() {
    int i = blockIdx.x * blockDim.x + threadIdx.x;
    if (i < N_NODES) g_dinv[i] = rsqrtf((float)(g_cnt[i] + 1));
}

// ---------------- CSR build: 3-phase scan + fill ----------------------------
__global__ void k_scan1() {
    __shared__ int sh[SCAN_B];
    int t = threadIdx.x;
    int i = blockIdx.x * SCAN_B + t;
    int v = (i < N_NODES) ? g_cnt[i] : 0;
    sh[t] = v;
    __syncthreads();
#pragma unroll
    for (int off = 1; off < SCAN_B; off <<= 1) {
        int x = (t >= off) ? sh[t - off] : 0;
        __syncthreads();
        sh[t] += x;
        __syncthreads();
    }
    if (i < N_NODES) g_rowptr[i] = sh[t] - v;
    if (t == SCAN_B - 1) g_bsum[blockIdx.x] = sh[t];
}
__global__ void k_scan2() {
    __shared__ int sh[256];
    int t = threadIdx.x;
    int v = (t < N_SBLK) ? g_bsum[t] : 0;
    sh[t] = v;
    __syncthreads();
#pragma unroll
    for (int off = 1; off < 256; off <<= 1) {
        int x = (t >= off) ? sh[t - off] : 0;
        __syncthreads();
        sh[t] += x;
        __syncthreads();
    }
    if (t < N_SBLK) g_boff[t] = sh[t] - v;
}
__global__ void k_scan3() {
    int i = blockIdx.x * blockDim.x + threadIdx.x;
    if (i < N_NODES) {
        int rp = g_rowptr[i] + g_boff[i / SCAN_B];
        g_rowptr[i] = rp;
        g_cursor[i] = rp;
    }
    if (i == 0) g_rowptr[N_NODES] = N_EDGES;
}
__global__ void k_fill(const int* __restrict__ ei) {
    int e = blockIdx.x * blockDim.x + threadIdx.x;
    if (e >= N_EDGES) return;
    int is64 = g_is64;
    int s = edge_at(ei, 0, e, is64);
    int d = edge_at(ei, 1, e, is64);
    int pos = atomicAdd(&g_cursor[d], 1);
    g_col[pos] = s;
}

// ---------------- layer-1 GEMM: pipelined bf16-split mma --------------------
// q1 = (X @ W1) * dinv[row].  BM=64, double-buffered smem, precomputed W1.
#define BM 64
#define BK 32
#define NKC (F_IN / BK)        // 8
// dynamic smem layout (bf16 element offsets)
#define A_STR 40               // 32 + 8 pad
#define B_STR 136              // 128 + 8 pad
#define A_BUF (BM * A_STR)     // 2560
#define B_BUF (BK * B_STR)     // 4352
#define OFF_AH 0
#define OFF_AL (2 * A_BUF)               // 5120
#define OFF_BH (4 * A_BUF)               // 10240
#define OFF_BL (4 * A_BUF + 2 * B_BUF)   // 18944
#define SMEM_G1_ELEMS (4 * A_BUF + 4 * B_BUF)   // 27648
#define SMEM_G1_BYTES (SMEM_G1_ELEMS * 2)       // 55296

__global__ __launch_bounds__(256, 2) void gemm1_mma(const float* __restrict__ X) {
    extern __shared__ __align__(16) char dsm_raw[];
    __nv_bfloat16* sm = (__nv_bfloat16*)dsm_raw;

    const int tid  = threadIdx.x;
    const int lane = tid & 31;
    const int wid  = tid >> 5;
    const int wm   = wid >> 2;       // 0..1  (32 rows each)
    const int wn   = wid & 3;        // 0..3  (32 cols each)
    const int rowBase = blockIdx.x * BM;

    // per-thread staging slots
    const int a_r0 = tid >> 3,        a_c4 = (tid & 7) * 4;       // +  a_r0+32
    const int b_k0 = tid >> 4,        b_n8 = (tid & 15) * 8;      // +  b_k0+16

    float4 stA[2];
    uint4  stBh[2], stBl[2];

    float acc[2][4][4];
#pragma unroll
    for (int mi = 0; mi < 2; mi++)
#pragma unroll
        for (int ni = 0; ni < 4; ni++)
#pragma unroll
            for (int r = 0; r < 4; r++) acc[mi][ni][r] = 0.f;

    // ---- stage loaders -----------------------------------------------------
    auto load_stage = [&](int kt) {
#pragma unroll
        for (int i = 0; i < 2; i++) {
            int gr = rowBase + a_r0 + i * 32;
            stA[i] = make_float4(0.f, 0.f, 0.f, 0.f);
            if (gr < N_NODES)
                stA[i] = *(const float4*)(X + (size_t)gr * F_IN + kt + a_c4);
        }
#pragma unroll
        for (int i = 0; i < 2; i++) {
            size_t off = (size_t)(kt + b_k0 + i * 16) * HID + b_n8;
            stBh[i] = *(const uint4*)(g_w1h + off);
            stBl[i] = *(const uint4*)(g_w1l + off);
        }
    };
    auto store_stage = [&](int buf) {
#pragma unroll
        for (int i = 0; i < 2; i++) {
            int r = a_r0 + i * 32;
            float4 v = stA[i];
            uint2 hh, ll;
            hh.x = pack_bf2(v.x, v.y); hh.y = pack_bf2(v.z, v.w);
            float lx = v.x - __bfloat162float(__float2bfloat16(v.x));
            float ly = v.y - __bfloat162float(__float2bfloat16(v.y));
            float lz = v.z - __bfloat162float(__float2bfloat16(v.z));
            float lw = v.w - __bfloat162float(__float2bfloat16(v.w));
            ll.x = pack_bf2(lx, ly); ll.y = pack_bf2(lz, lw);
            int idx = buf * A_BUF + r * A_STR + a_c4;
            *(uint2*)&sm[OFF_AH + idx] = hh;
            *(uint2*)&sm[OFF_AL + idx] = ll;
        }
#pragma unroll
        for (int i = 0; i < 2; i++) {
            int k = b_k0 + i * 16;
            int idx = buf * B_BUF + k * B_STR + b_n8;
            *(uint4*)&sm[OFF_BH + idx] = stBh[i];
            *(uint4*)&sm[OFF_BL + idx] = stBl[i];
        }
    };

    load_stage(0);
    store_stage(0);
    __syncthreads();

    for (int kc = 0; kc < NKC; kc++) {
        int buf = kc & 1;
        if (kc + 1 < NKC) load_stage((kc + 1) * BK);   // LDGs in flight

#pragma unroll
        for (int ks = 0; ks < 2; ks++) {
            int k16 = ks * 16;
            uint32_t ah[2][4], al[2][4], bh[4][2], bl[4][2];
#pragma unroll
            for (int mi = 0; mi < 2; mi++) {
                int row = wm * 32 + mi * 16 + (lane & 15);
                int col = k16 + (lane >> 4) * 8;
                int idx = buf * A_BUF + row * A_STR + col;
                LDSM_X4(ah[mi], smem_addr(&sm[OFF_AH + idx]));
                LDSM_X4(al[mi], smem_addr(&sm[OFF_AL + idx]));
            }
#pragma unroll
            for (int ni = 0; ni < 4; ni++) {
                int krow = k16 + (lane & 15);
                int col  = wn * 32 + ni * 8;
                int idx = buf * B_BUF + krow * B_STR + col;
                LDSM_X2T(bh[ni], smem_addr(&sm[OFF_BH + idx]));
                LDSM_X2T(bl[ni], smem_addr(&sm[OFF_BL + idx]));
            }
#pragma unroll
            for (int mi = 0; mi < 2; mi++)
#pragma unroll
                for (int ni = 0; ni < 4; ni++) {
                    MMA_BF16(acc[mi][ni], ah[mi], bh[ni]);
                    MMA_BF16(acc[mi][ni], ah[mi], bl[ni]);
                    MMA_BF16(acc[mi][ni], al[mi], bh[ni]);
                }
        }
        if (kc + 1 < NKC) store_stage(buf ^ 1);
        __syncthreads();
    }

    const int rBase = rowBase + wm * 32 + (lane >> 2);
    const int cBase = wn * 32 + (lane & 3) * 2;
#pragma unroll
    for (int mi = 0; mi < 2; mi++) {
        int gr0 = rBase + mi * 16;
        int gr1 = gr0 + 8;
        float d0 = (gr0 < N_NODES) ? g_dinv[gr0] : 0.f;
        float d1 = (gr1 < N_NODES) ? g_dinv[gr1] : 0.f;
#pragma unroll
        for (int ni = 0; ni < 4; ni++) {
            int gc = cBase + ni * 8;
            if (gr0 < N_NODES)
                *(float2*)(g_q1 + (size_t)gr0 * HID + gc) =
                    make_float2(acc[mi][ni][0] * d0, acc[mi][ni][1] * d0);
            if (gr1 < N_NODES)
                *(float2*)(g_q1 + (size_t)gr1 * HID + gc) =
                    make_float2(acc[mi][ni][2] * d1, acc[mi][ni][3] * d1);
        }
    }
}

// ---------------- CSR aggregation layer 1 (index-prefetch gather) -----------
__global__ void k_agg1(const float* __restrict__ b1) {
    int node = blockIdx.x * (blockDim.x >> 5) + (threadIdx.x >> 5);
    int lane = threadIdx.x & 31;
    if (node >= N_NODES) return;
    int start = g_rowptr[node];
    int deg   = g_rowptr[node + 1] - start;

    const float4* q1v = (const float4*)g_q1;
    float4 acc = q1v[(size_t)node * 32 + lane];      // self term

    int myidx = (lane < deg) ? g_col[start + lane] : 0;
    int n32 = deg < 32 ? deg : 32;
    int e = 0;
    for (; e + 4 <= n32; e += 4) {
        int s0 = __shfl_sync(0xffffffffu, myidx, e);
        int s1 = __shfl_sync(0xffffffffu, myidx, e + 1);
        int s2 = __shfl_sync(0xffffffffu, myidx, e + 2);
        int s3 = __shfl_sync(0xffffffffu, myidx, e + 3);
        float4 v0 = q1v[(size_t)s0 * 32 + lane];
        float4 v1 = q1v[(size_t)s1 * 32 + lane];
        float4 v2 = q1v[(size_t)s2 * 32 + lane];
        float4 v3 = q1v[(size_t)s3 * 32 + lane];
        acc.x += (v0.x + v1.x) + (v2.x + v3.x);
        acc.y += (v0.y + v1.y) + (v2.y + v3.y);
        acc.z += (v0.z + v1.z) + (v2.z + v3.z);
        acc.w += (v0.w + v1.w) + (v2.w + v3.w);
    }
    for (; e < n32; e++) {
        int s = __shfl_sync(0xffffffffu, myidx, e);
        float4 v = q1v[(size_t)s * 32 + lane];
        acc.x += v.x; acc.y += v.y; acc.z += v.z; acc.w += v.w;
    }
    for (e = 32; e < deg; e++) {
        int s = g_col[start + e];
        float4 v = q1v[(size_t)s * 32 + lane];
        acc.x += v.x; acc.y += v.y; acc.z += v.z; acc.w += v.w;
    }

    float d = g_dinv[node];
    float4 b = ((const float4*)b1)[lane];
    float4 o;
    o.x = fmaxf(fmaf(acc.x, d, b.x), 0.f);
    o.y = fmaxf(fmaf(acc.y, d, b.y), 0.f);
    o.z = fmaxf(fmaf(acc.z, d, b.z), 0.f);
    o.w = fmaxf(fmaf(acc.w, d, b.w), 0.f);
    ((float4*)(g_h1 + (size_t)node * HID))[lane] = o;
}

// ---------------- layer-2 GEMM: bf16-split mma, precomputed W2 --------------
// q2 = (h1 @ W2) * dinv[row];  M tiles of 128, N=32, K=128
#define APAD 8
#define BPAD 8
__global__ __launch_bounds__(256, 2) void gemm2_mma() {
    __shared__ __align__(16) __nv_bfloat16 sAh[128][BK + APAD];
    __shared__ __align__(16) __nv_bfloat16 sAl[128][BK + APAD];
    __shared__ __align__(16) __nv_bfloat16 sBh[BK][CLS + BPAD];
    __shared__ __align__(16) __nv_bfloat16 sBl[BK][CLS + BPAD];

    const int tid  = threadIdx.x;
    const int lane = tid & 31;
    const int wid  = tid >> 5;
    const int rowBase = blockIdx.x * 128;

    float acc[4][4];
#pragma unroll
    for (int ni = 0; ni < 4; ni++)
#pragma unroll
        for (int r = 0; r < 4; r++) acc[ni][r] = 0.f;

    for (int kt = 0; kt < HID; kt += BK) {
#pragma unroll
        for (int i = 0; i < 4; i++) {
            int idx = tid + i * 256;
            int r = idx >> 3, c4 = (idx & 7) * 4;
            int gr = rowBase + r;
            float4 v = make_float4(0.f, 0.f, 0.f, 0.f);
            if (gr < N_NODES)
                v = *(const float4*)(g_h1 + (size_t)gr * HID + kt + c4);
            uint2 hh, ll;
            hh.x = pack_bf2(v.x, v.y); hh.y = pack_bf2(v.z, v.w);
            float lx = v.x - __bfloat162float(__float2bfloat16(v.x));
            float ly = v.y - __bfloat162float(__float2bfloat16(v.y));
            float lz = v.z - __bfloat162float(__float2bfloat16(v.z));
            float lw = v.w - __bfloat162float(__float2bfloat16(v.w));
            ll.x = pack_bf2(lx, ly); ll.y = pack_bf2(lz, lw);
            *(uint2*)&sAh[r][c4] = hh;
            *(uint2*)&sAl[r][c4] = ll;
        }
        if (tid < 128) {   // B tile: 32x32 bf16 = 128 uint4 per array
            int k = tid >> 2, n8 = (tid & 3) * 8;
            size_t off = (size_t)(kt + k) * CLS + n8;
            *(uint4*)&sBh[k][n8] = *(const uint4*)(g_w2h + off);
            *(uint4*)&sBl[k][n8] = *(const uint4*)(g_w2l + off);
        }
        __syncthreads();

#pragma unroll
        for (int ks = 0; ks < BK / 16; ks++) {
            int k16 = ks * 16;
            uint32_t ah[4], al[4], bh[4][2], bl[4][2];
            {
                int row = wid * 16 + (lane & 15);
                int col = k16 + (lane >> 4) * 8;
                LDSM_X4(ah, smem_addr(&sAh[row][col]));
                LDSM_X4(al, smem_addr(&sAl[row][col]));
            }
#pragma unroll
            for (int ni = 0; ni < 4; ni++) {
                int krow = k16 + (lane & 15);
                int col  = ni * 8;
                LDSM_X2T(bh[ni], smem_addr(&sBh[krow][col]));
                LDSM_X2T(bl[ni], smem_addr(&sBl[krow][col]));
            }
#pragma unroll
            for (int ni = 0; ni < 4; ni++) {
                MMA_BF16(acc[ni], ah, bh[ni]);
                MMA_BF16(acc[ni], ah, bl[ni]);
                MMA_BF16(acc[ni], al, bh[ni]);
            }
        }
        __syncthreads();
    }

    const int r0 = rowBase + wid * 16 + (lane >> 2);
    const int r1 = r0 + 8;
    const int cBase = (lane & 3) * 2;
    float d0 = (r0 < N_NODES) ? g_dinv[r0] : 0.f;
    float d1 = (r1 < N_NODES) ? g_dinv[r1] : 0.f;
#pragma unroll
    for (int ni = 0; ni < 4; ni++) {
        int gc = cBase + ni * 8;
        if (r0 < N_NODES)
            *(float2*)(g_q2 + (size_t)r0 * CLS + gc) =
                make_float2(acc[ni][0] * d0, acc[ni][1] * d0);
        if (r1 < N_NODES)
            *(float2*)(g_q2 + (size_t)r1 * CLS + gc) =
                make_float2(acc[ni][2] * d1, acc[ni][3] * d1);
    }
}

// ---------------- CSR aggregation layer 2 (fused bias+logsoftmax) -----------
__global__ void k_agg2(const float* __restrict__ b2,
                       float* __restrict__ out) {
    int node = blockIdx.x * (blockDim.x >> 5) + (threadIdx.x >> 5);
    int lane = threadIdx.x & 31;
    if (node >= N_NODES) return;
    int start = g_rowptr[node];
    int deg   = g_rowptr[node + 1] - start;

    float acc = g_q2[(size_t)node * CLS + lane];     // self term

    int myidx = (lane < deg) ? g_col[start + lane] : 0;
    int n32 = deg < 32 ? deg : 32;
    int e = 0;
    for (; e + 4 <= n32; e += 4) {
        int s0 = __shfl_sync(0xffffffffu, myidx, e);
        int s1 = __shfl_sync(0xffffffffu, myidx, e + 1);
        int s2 = __shfl_sync(0xffffffffu, myidx, e + 2);
        int s3 = __shfl_sync(0xffffffffu, myidx, e + 3);
        float v0 = g_q2[(size_t)s0 * CLS + lane];
        float v1 = g_q2[(size_t)s1 * CLS + lane];
        float v2 = g_q2[(size_t)s2 * CLS + lane];
        float v3 = g_q2[(size_t)s3 * CLS + lane];
        acc += (v0 + v1) + (v2 + v3);
    }
    for (; e < n32; e++) {
        int s = __shfl_sync(0xffffffffu, myidx, e);
        acc += g_q2[(size_t)s * CLS + lane];
    }
    for (e = 32; e < deg; e++)
        acc += g_q2[(size_t)g_col[start + e] * CLS + lane];

    float v = fmaf(acc, g_dinv[node], b2[lane]);
    float m = v;
#pragma unroll
    for (int o = 16; o > 0; o >>= 1) m = fmaxf(m, __shfl_xor_sync(0xffffffffu, m, o));
    float ex = __expf(v - m);
    float ssum = ex;
#pragma unroll
    for (int o = 16; o > 0; o >>= 1) ssum += __shfl_xor_sync(0xffffffffu, ssum, o);
    out[(size_t)node * CLS + lane] = v - m - __logf(ssum);
}

// ---------------- launch -----------------------------------------------------
extern "C" void kernel_launch(void* const* d_in, const int* in_sizes, int n_in,
                              void* d_out, int out_size) {
    const float* X   = (const float*)d_in[0];
    const int*   ei  = (const int*)d_in[1];
    const float* W1  = (const float*)d_in[2];
    const float* b1  = (const float*)d_in[3];
    const float* W2  = (const float*)d_in[4];
    const float* b2  = (const float*)d_in[5];
    float*       out = (float*)d_out;

    cudaFuncSetAttribute(gemm1_mma, cudaFuncAttributeMaxDynamicSharedMemorySize,
                         SMEM_G1_BYTES);

    const int TB = 256;
    const int nodeGrid = (N_NODES + TB - 1) / TB;
    const int edgeGrid = (N_EDGES + TB - 1) / TB;
    const int convGrid = (F_IN * HID + TB - 1) / TB;
    const bool fork = g_s2 && g_e0 && g_e1 && g_e2;

    if (fork) {
        cudaEventRecord(g_e0, 0);
        cudaStreamWaitEvent(g_s2, g_e0, 0);
        k_convw<<<convGrid, TB, 0, g_s2>>>(W1, W2);   // overlaps degree count
    } else {
        k_convw<<<convGrid, TB>>>(W1, W2);
    }

    // degree + dinv on main stream
    k_zero_cnt   <<<nodeGrid, TB>>>(ei);
    k_cnt_scatter<<<edgeGrid, TB>>>(ei);
    k_dinv       <<<nodeGrid, TB>>>();

    // fork: GEMM1 on side stream (needs convw + dinv), CSR scan/fill on main
    if (fork) {
        cudaEventRecord(g_e1, 0);
        cudaStreamWaitEvent(g_s2, g_e1, 0);
        gemm1_mma<<<(N_NODES + BM - 1) / BM, 256, SMEM_G1_BYTES, g_s2>>>(X);
        cudaEventRecord(g_e2, g_s2);
    } else {
        gemm1_mma<<<(N_NODES + BM - 1) / BM, 256, SMEM_G1_BYTES>>>(X);
    }

    k_scan1<<<N_SBLK, SCAN_B>>>();
    k_scan2<<<1, 256>>>();
    k_scan3<<<nodeGrid, TB>>>();
    k_fill <<<edgeGrid, TB>>>(ei);

    if (fork) cudaStreamWaitEvent(0, g_e2, 0);   // join before agg1

    k_agg1   <<<(N_NODES * 32 + TB - 1) / TB, TB>>>(b1);
    gemm2_mma<<<(N_NODES + 127) / 128, 256>>>();
    k_agg2   <<<(N_NODES * 32 + TB - 1) / TB, TB>>>(b2, out);
}

// round 11
// speedup vs baseline: 1.8173x; 1.0002x over previous
#include <cuda_runtime.h>
#include <cuda_bf16.h>
#include <cstdint>

#define N_NODES 100000
#define N_EDGES 800000
#define F_IN    256
#define HID     128
#define CLS     32
#define SCAN_B  512
#define N_SBLK  ((N_NODES + SCAN_B - 1) / SCAN_B)   // 196

// ---------------- scratch (device globals: no allocation allowed) ----------
__device__ int   g_cnt[N_NODES];
__device__ float g_dinv[N_NODES];
__device__ int   g_rowptr[N_NODES + 1];
__device__ int   g_cursor[N_NODES];
__device__ int   g_col[N_EDGES];
__device__ int   g_bsum[N_SBLK];
__device__ int   g_boff[N_SBLK];
__device__ float g_q1 [(size_t)N_NODES * HID];   // raw xw1 (NO dinv prescale)
__device__ float g_h1 [(size_t)N_NODES * HID];
__device__ float g_q2 [(size_t)N_NODES * CLS];   // xw2 * dinv[row]
__device__ __nv_bfloat16 g_w1h[F_IN * HID];
__device__ __nv_bfloat16 g_w1l[F_IN * HID];
__device__ __nv_bfloat16 g_w2h[HID * CLS];
__device__ __nv_bfloat16 g_w2l[HID * CLS];
__device__ int   g_is64;

// ---------------- stream/events for fork-join overlap (created at load) -----
static cudaStream_t g_s2 = nullptr;
static cudaEvent_t  g_e0 = nullptr, g_e2 = nullptr;
namespace {
struct HxStreamInit {
    HxStreamInit() {
        cudaStreamCreateWithFlags(&g_s2, cudaStreamNonBlocking);
        cudaEventCreateWithFlags(&g_e0, cudaEventDisableTiming);
        cudaEventCreateWithFlags(&g_e2, cudaEventDisableTiming);
    }
};
static HxStreamInit g_hx_stream_init;
}

// ---------------- helpers ----------------------------------------------------
__device__ __forceinline__ uint32_t smem_addr(const void* p) {
    return (uint32_t)__cvta_generic_to_shared(p);
}
#define LDSM_X4(r, a)                                                          \
    asm volatile("ldmatrix.sync.aligned.m8n8.x4.shared.b16 {%0,%1,%2,%3}, [%4];" \
                 : "=r"((r)[0]), "=r"((r)[1]), "=r"((r)[2]), "=r"((r)[3])      \
                 : "r"(a))
#define LDSM_X2T(r, a)                                                         \
    asm volatile("ldmatrix.sync.aligned.m8n8.x2.trans.shared.b16 {%0,%1}, [%2];" \
                 : "=r"((r)[0]), "=r"((r)[1]) : "r"(a))
#define MMA_BF16(c, a, b)                                                      \
    asm volatile("mma.sync.aligned.m16n8k16.row.col.f32.bf16.bf16.f32 "        \
                 "{%0,%1,%2,%3}, {%4,%5,%6,%7}, {%8,%9}, {%0,%1,%2,%3};"       \
                 : "+f"((c)[0]), "+f"((c)[1]), "+f"((c)[2]), "+f"((c)[3])      \
                 : "r"((a)[0]), "r"((a)[1]), "r"((a)[2]), "r"((a)[3]),         \
                   "r"((b)[0]), "r"((b)[1]))

__device__ __forceinline__ int edge_at(const int* __restrict__ ei,
                                       int which, int e, int is64) {
    size_t base = (size_t)which * N_EDGES + (size_t)e;
    return is64 ? ei[base * 2] : ei[base];
}
__device__ __forceinline__ uint32_t pack_bf2(float a, float b) {
    __nv_bfloat162 p = make_bfloat162(__float2bfloat16(a), __float2bfloat16(b));
    return *(uint32_t*)&p;
}

// ---------------- weight conversion (hi/lo bf16 split) ----------------------
__global__ void k_convw(const float* __restrict__ W1,
                        const float* __restrict__ W2) {
    int i = blockIdx.x * blockDim.x + threadIdx.x;
    if (i < F_IN * HID) {
        float x = W1[i];
        __nv_bfloat16 h = __float2bfloat16(x);
        g_w1h[i] = h;
        g_w1l[i] = __float2bfloat16(x - __bfloat162float(h));
    }
    if (i < HID * CLS) {
        float x = W2[i];
        __nv_bfloat16 h = __float2bfloat16(x);
        g_w2h[i] = h;
        g_w2l[i] = __float2bfloat16(x - __bfloat162float(h));
    }
}

// ---------------- degree count (+ dtype probe fused) ------------------------
__global__ void k_zero_cnt(const int* __restrict__ ei) {
    int i = blockIdx.x * blockDim.x + threadIdx.x;
    if (i < N_NODES) g_cnt[i] = 0;
    if (i == 0) {
        int is64 = 1;
        for (int j = 0; j < 64; j++)
            if (ei[2 * j + 1] != 0) { is64 = 0; break; }
        g_is64 = is64;
    }
}
__global__ void k_cnt_scatter(const int* __restrict__ ei) {
    int e = blockIdx.x * blockDim.x + threadIdx.x;
    if (e >= N_EDGES) return;
    atomicAdd(&g_cnt[edge_at(ei, 1, e, g_is64)], 1);
}

// ---------------- CSR build: 3-phase scan (+dinv fused) + fill --------------
__global__ void k_scan1() {
    __shared__ int sh[SCAN_B];
    int t = threadIdx.x;
    int i = blockIdx.x * SCAN_B + t;
    int v = (i < N_NODES) ? g_cnt[i] : 0;
    sh[t] = v;
    __syncthreads();
#pragma unroll
    for (int off = 1; off < SCAN_B; off <<= 1) {
        int x = (t >= off) ? sh[t - off] : 0;
        __syncthreads();
        sh[t] += x;
        __syncthreads();
    }
    if (i < N_NODES) g_rowptr[i] = sh[t] - v;
    if (t == SCAN_B - 1) g_bsum[blockIdx.x] = sh[t];
}
__global__ void k_scan2() {
    __shared__ int sh[256];
    int t = threadIdx.x;
    int v = (t < N_SBLK) ? g_bsum[t] : 0;
    sh[t] = v;
    __syncthreads();
#pragma unroll
    for (int off = 1; off < 256; off <<= 1) {
        int x = (t >= off) ? sh[t - off] : 0;
        __syncthreads();
        sh[t] += x;
        __syncthreads();
    }
    if (t < N_SBLK) g_boff[t] = sh[t] - v;
}
__global__ void k_scan3() {
    int i = blockIdx.x * blockDim.x + threadIdx.x;
    if (i < N_NODES) {
        int rp = g_rowptr[i] + g_boff[i / SCAN_B];
        g_rowptr[i] = rp;
        g_cursor[i] = rp;
        g_dinv[i]   = rsqrtf((float)(g_cnt[i] + 1));   // +1 self loop
    }
    if (i == 0) g_rowptr[N_NODES] = N_EDGES;
}
__global__ void k_fill(const int* __restrict__ ei) {
    int e = blockIdx.x * blockDim.x + threadIdx.x;
    if (e >= N_EDGES) return;
    int is64 = g_is64;
    int s = edge_at(ei, 0, e, is64);
    int d = edge_at(ei, 1, e, is64);
    int pos = atomicAdd(&g_cursor[d], 1);
    g_col[pos] = s;
}

// ---------------- layer-1 GEMM: pipelined bf16-split mma --------------------
// q1 = X @ W1  (raw, no dinv — lets gemm1 run independent of the degree chain)
#define BM 64
#define BK 32
#define NKC (F_IN / BK)        // 8
#define A_STR 40
#define B_STR 136
#define A_BUF (BM * A_STR)
#define B_BUF (BK * B_STR)
#define OFF_AH 0
#define OFF_AL (2 * A_BUF)
#define OFF_BH (4 * A_BUF)
#define OFF_BL (4 * A_BUF + 2 * B_BUF)
#define SMEM_G1_ELEMS (4 * A_BUF + 4 * B_BUF)
#define SMEM_G1_BYTES (SMEM_G1_ELEMS * 2)       // 55296

__global__ __launch_bounds__(256, 2) void gemm1_mma(const float* __restrict__ X) {
    extern __shared__ __align__(16) char dsm_raw[];
    __nv_bfloat16* sm = (__nv_bfloat16*)dsm_raw;

    const int tid  = threadIdx.x;
    const int lane = tid & 31;
    const int wid  = tid >> 5;
    const int wm   = wid >> 2;
    const int wn   = wid & 3;
    const int rowBase = blockIdx.x * BM;

    const int a_r0 = tid >> 3,  a_c4 = (tid & 7) * 4;
    const int b_k0 = tid >> 4,  b_n8 = (tid & 15) * 8;

    float4 stA[2];
    uint4  stBh[2], stBl[2];

    float acc[2][4][4];
#pragma unroll
    for (int mi = 0; mi < 2; mi++)
#pragma unroll
        for (int ni = 0; ni < 4; ni++)
#pragma unroll
            for (int r = 0; r < 4; r++) acc[mi][ni][r] = 0.f;

    auto load_stage = [&](int kt) {
#pragma unroll
        for (int i = 0; i < 2; i++) {
            int gr = rowBase + a_r0 + i * 32;
            stA[i] = make_float4(0.f, 0.f, 0.f, 0.f);
            if (gr < N_NODES)
                stA[i] = *(const float4*)(X + (size_t)gr * F_IN + kt + a_c4);
        }
#pragma unroll
        for (int i = 0; i < 2; i++) {
            size_t off = (size_t)(kt + b_k0 + i * 16) * HID + b_n8;
            stBh[i] = *(const uint4*)(g_w1h + off);
            stBl[i] = *(const uint4*)(g_w1l + off);
        }
    };
    auto store_stage = [&](int buf) {
#pragma unroll
        for (int i = 0; i < 2; i++) {
            int r = a_r0 + i * 32;
            float4 v = stA[i];
            uint2 hh, ll;
            hh.x = pack_bf2(v.x, v.y); hh.y = pack_bf2(v.z, v.w);
            float lx = v.x - __bfloat162float(__float2bfloat16(v.x));
            float ly = v.y - __bfloat162float(__float2bfloat16(v.y));
            float lz = v.z - __bfloat162float(__float2bfloat16(v.z));
            float lw = v.w - __bfloat162float(__float2bfloat16(v.w));
            ll.x = pack_bf2(lx, ly); ll.y = pack_bf2(lz, lw);
            int idx = buf * A_BUF + r * A_STR + a_c4;
            *(uint2*)&sm[OFF_AH + idx] = hh;
            *(uint2*)&sm[OFF_AL + idx] = ll;
        }
#pragma unroll
        for (int i = 0; i < 2; i++) {
            int k = b_k0 + i * 16;
            int idx = buf * B_BUF + k * B_STR + b_n8;
            *(uint4*)&sm[OFF_BH + idx] = stBh[i];
            *(uint4*)&sm[OFF_BL + idx] = stBl[i];
        }
    };

    load_stage(0);
    store_stage(0);
    __syncthreads();

    for (int kc = 0; kc < NKC; kc++) {
        int buf = kc & 1;
        if (kc + 1 < NKC) load_stage((kc + 1) * BK);

#pragma unroll
        for (int ks = 0; ks < 2; ks++) {
            int k16 = ks * 16;
            uint32_t ah[2][4], al[2][4], bh[4][2], bl[4][2];
#pragma unroll
            for (int mi = 0; mi < 2; mi++) {
                int row = wm * 32 + mi * 16 + (lane & 15);
                int col = k16 + (lane >> 4) * 8;
                int idx = buf * A_BUF + row * A_STR + col;
                LDSM_X4(ah[mi], smem_addr(&sm[OFF_AH + idx]));
                LDSM_X4(al[mi], smem_addr(&sm[OFF_AL + idx]));
            }
#pragma unroll
            for (int ni = 0; ni < 4; ni++) {
                int krow = k16 + (lane & 15);
                int col  = wn * 32 + ni * 8;
                int idx = buf * B_BUF + krow * B_STR + col;
                LDSM_X2T(bh[ni], smem_addr(&sm[OFF_BH + idx]));
                LDSM_X2T(bl[ni], smem_addr(&sm[OFF_BL + idx]));
            }
#pragma unroll
            for (int mi = 0; mi < 2; mi++)
#pragma unroll
                for (int ni = 0; ni < 4; ni++) {
                    MMA_BF16(acc[mi][ni], ah[mi], bh[ni]);
                    MMA_BF16(acc[mi][ni], ah[mi], bl[ni]);
                    MMA_BF16(acc[mi][ni], al[mi], bh[ni]);
                }
        }
        if (kc + 1 < NKC) store_stage(buf ^ 1);
        __syncthreads();
    }

    const int rBase = rowBase + wm * 32 + (lane >> 2);
    const int cBase = wn * 32 + (lane & 3) * 2;
#pragma unroll
    for (int mi = 0; mi < 2; mi++) {
        int gr0 = rBase + mi * 16;
        int gr1 = gr0 + 8;
#pragma unroll
        for (int ni = 0; ni < 4; ni++) {
            int gc = cBase + ni * 8;
            if (gr0 < N_NODES)
                *(float2*)(g_q1 + (size_t)gr0 * HID + gc) =
                    make_float2(acc[mi][ni][0], acc[mi][ni][1]);
            if (gr1 < N_NODES)
                *(float2*)(g_q1 + (size_t)gr1 * HID + gc) =
                    make_float2(acc[mi][ni][2], acc[mi][ni][3]);
        }
    }
}

// ---------------- CSR aggregation layer 1 (per-edge dinv scaling) -----------
// h1[i] = relu(dinv[i] * (xw1[i]*dinv[i] + sum_e xw1[col[e]]*dinv[col[e]]) + b1)
__global__ void k_agg1(const float* __restrict__ b1) {
    int node = blockIdx.x * (blockDim.x >> 5) + (threadIdx.x >> 5);
    int lane = threadIdx.x & 31;
    if (node >= N_NODES) return;
    int start = g_rowptr[node];
    int deg   = g_rowptr[node + 1] - start;
    float d = g_dinv[node];

    const float4* q1v = (const float4*)g_q1;
    float4 sv = q1v[(size_t)node * 32 + lane];       // self term
    float4 acc;
    acc.x = sv.x * d; acc.y = sv.y * d; acc.z = sv.z * d; acc.w = sv.w * d;

    int myidx = (lane < deg) ? g_col[start + lane] : 0;
    int n32 = deg < 32 ? deg : 32;
    int e = 0;
    for (; e + 4 <= n32; e += 4) {
        int s0 = __shfl_sync(0xffffffffu, myidx, e);
        int s1 = __shfl_sync(0xffffffffu, myidx, e + 1);
        int s2 = __shfl_sync(0xffffffffu, myidx, e + 2);
        int s3 = __shfl_sync(0xffffffffu, myidx, e + 3);
        float d0 = g_dinv[s0], d1 = g_dinv[s1], d2 = g_dinv[s2], d3 = g_dinv[s3];
        float4 v0 = q1v[(size_t)s0 * 32 + lane];
        float4 v1 = q1v[(size_t)s1 * 32 + lane];
        float4 v2 = q1v[(size_t)s2 * 32 + lane];
        float4 v3 = q1v[(size_t)s3 * 32 + lane];
        acc.x += (v0.x * d0 + v1.x * d1) + (v2.x * d2 + v3.x * d3);
        acc.y += (v0.y * d0 + v1.y * d1) + (v2.y * d2 + v3.y * d3);
        acc.z += (v0.z * d0 + v1.z * d1) + (v2.z * d2 + v3.z * d3);
        acc.w += (v0.w * d0 + v1.w * d1) + (v2.w * d2 + v3.w * d3);
    }
    for (; e < n32; e++) {
        int s = __shfl_sync(0xffffffffu, myidx, e);
        float ds = g_dinv[s];
        float4 v = q1v[(size_t)s * 32 + lane];
        acc.x += v.x * ds; acc.y += v.y * ds; acc.z += v.z * ds; acc.w += v.w * ds;
    }
    for (e = 32; e < deg; e++) {
        int s = g_col[start + e];
        float ds = g_dinv[s];
        float4 v = q1v[(size_t)s * 32 + lane];
        acc.x += v.x * ds; acc.y += v.y * ds; acc.z += v.z * ds; acc.w += v.w * ds;
    }

    float4 b = ((const float4*)b1)[lane];
    float4 o;
    o.x = fmaxf(fmaf(acc.x, d, b.x), 0.f);
    o.y = fmaxf(fmaf(acc.y, d, b.y), 0.f);
    o.z = fmaxf(fmaf(acc.z, d, b.z), 0.f);
    o.w = fmaxf(fmaf(acc.w, d, b.w), 0.f);
    ((float4*)(g_h1 + (size_t)node * HID))[lane] = o;
}

// ---------------- layer-2 GEMM: bf16-split mma, precomputed W2 --------------
// q2 = (h1 @ W2) * dinv[row];  M tiles of 128, N=32, K=128
#define APAD 8
#define BPAD 8
__global__ __launch_bounds__(256, 2) void gemm2_mma() {
    __shared__ __align__(16) __nv_bfloat16 sAh[128][BK + APAD];
    __shared__ __align__(16) __nv_bfloat16 sAl[128][BK + APAD];
    __shared__ __align__(16) __nv_bfloat16 sBh[BK][CLS + BPAD];
    __shared__ __align__(16) __nv_bfloat16 sBl[BK][CLS + BPAD];

    const int tid  = threadIdx.x;
    const int lane = tid & 31;
    const int wid  = tid >> 5;
    const int rowBase = blockIdx.x * 128;

    float acc[4][4];
#pragma unroll
    for (int ni = 0; ni < 4; ni++)
#pragma unroll
        for (int r = 0; r < 4; r++) acc[ni][r] = 0.f;

    for (int kt = 0; kt < HID; kt += BK) {
#pragma unroll
        for (int i = 0; i < 4; i++) {
            int idx = tid + i * 256;
            int r = idx >> 3, c4 = (idx & 7) * 4;
            int gr = rowBase + r;
            float4 v = make_float4(0.f, 0.f, 0.f, 0.f);
            if (gr < N_NODES)
                v = *(const float4*)(g_h1 + (size_t)gr * HID + kt + c4);
            uint2 hh, ll;
            hh.x = pack_bf2(v.x, v.y); hh.y = pack_bf2(v.z, v.w);
            float lx = v.x - __bfloat162float(__float2bfloat16(v.x));
            float ly = v.y - __bfloat162float(__float2bfloat16(v.y));
            float lz = v.z - __bfloat162float(__float2bfloat16(v.z));
            float lw = v.w - __bfloat162float(__float2bfloat16(v.w));
            ll.x = pack_bf2(lx, ly); ll.y = pack_bf2(lz, lw);
            *(uint2*)&sAh[r][c4] = hh;
            *(uint2*)&sAl[r][c4] = ll;
        }
        if (tid < 128) {
            int k = tid >> 2, n8 = (tid & 3) * 8;
            size_t off = (size_t)(kt + k) * CLS + n8;
            *(uint4*)&sBh[k][n8] = *(const uint4*)(g_w2h + off);
            *(uint4*)&sBl[k][n8] = *(const uint4*)(g_w2l + off);
        }
        __syncthreads();

#pragma unroll
        for (int ks = 0; ks < BK / 16; ks++) {
            int k16 = ks * 16;
            uint32_t ah[4], al[4], bh[4][2], bl[4][2];
            {
                int row = wid * 16 + (lane & 15);
                int col = k16 + (lane >> 4) * 8;
                LDSM_X4(ah, smem_addr(&sAh[row][col]));
                LDSM_X4(al, smem_addr(&sAl[row][col]));
            }
#pragma unroll
            for (int ni = 0; ni < 4; ni++) {
                int krow = k16 + (lane & 15);
                int col  = ni * 8;
                LDSM_X2T(bh[ni], smem_addr(&sBh[krow][col]));
                LDSM_X2T(bl[ni], smem_addr(&sBl[krow][col]));
            }
#pragma unroll
            for (int ni = 0; ni < 4; ni++) {
                MMA_BF16(acc[ni], ah, bh[ni]);
                MMA_BF16(acc[ni], ah, bl[ni]);
                MMA_BF16(acc[ni], al, bh[ni]);
            }
        }
        __syncthreads();
    }

    const int r0 = rowBase + wid * 16 + (lane >> 2);
    const int r1 = r0 + 8;
    const int cBase = (lane & 3) * 2;
    float d0 = (r0 < N_NODES) ? g_dinv[r0] : 0.f;
    float d1 = (r1 < N_NODES) ? g_dinv[r1] : 0.f;
#pragma unroll
    for (int ni = 0; ni < 4; ni++) {
        int gc = cBase + ni * 8;
        if (r0 < N_NODES)
            *(float2*)(g_q2 + (size_t)r0 * CLS + gc) =
                make_float2(acc[ni][0] * d0, acc[ni][1] * d0);
        if (r1 < N_NODES)
            *(float2*)(g_q2 + (size_t)r1 * CLS + gc) =
                make_float2(acc[ni][2] * d1, acc[ni][3] * d1);
    }
}

// ---------------- CSR aggregation layer 2 (fused bias+logsoftmax) -----------
__global__ void k_agg2(const float* __restrict__ b2,
                       float* __restrict__ out) {
    int node = blockIdx.x * (blockDim.x >> 5) + (threadIdx.x >> 5);
    int lane = threadIdx.x & 31;
    if (node >= N_NODES) return;
    int start = g_rowptr[node];
    int deg   = g_rowptr[node + 1] - start;

    float acc = g_q2[(size_t)node * CLS + lane];     // self term

    int myidx = (lane < deg) ? g_col[start + lane] : 0;
    int n32 = deg < 32 ? deg : 32;
    int e = 0;
    for (; e + 4 <= n32; e += 4) {
        int s0 = __shfl_sync(0xffffffffu, myidx, e);
        int s1 = __shfl_sync(0xffffffffu, myidx, e + 1);
        int s2 = __shfl_sync(0xffffffffu, myidx, e + 2);
        int s3 = __shfl_sync(0xffffffffu, myidx, e + 3);
        float v0 = g_q2[(size_t)s0 * CLS + lane];
        float v1 = g_q2[(size_t)s1 * CLS + lane];
        float v2 = g_q2[(size_t)s2 * CLS + lane];
        float v3 = g_q2[(size_t)s3 * CLS + lane];
        acc += (v0 + v1) + (v2 + v3);
    }
    for (; e < n32; e++) {
        int s = __shfl_sync(0xffffffffu, myidx, e);
        acc += g_q2[(size_t)s * CLS + lane];
    }
    for (e = 32; e < deg; e++)
        acc += g_q2[(size_t)g_col[start + e] * CLS + lane];

    float v = fmaf(acc, g_dinv[node], b2[lane]);
    float m = v;
#pragma unroll
    for (int o = 16; o > 0; o >>= 1) m = fmaxf(m, __shfl_xor_sync(0xffffffffu, m, o));
    float ex = __expf(v - m);
    float ssum = ex;
#pragma unroll
    for (int o = 16; o > 0; o >>= 1) ssum += __shfl_xor_sync(0xffffffffu, ssum, o);
    out[(size_t)node * CLS + lane] = v - m - __logf(ssum);
}

// ---------------- launch -----------------------------------------------------
extern "C" void kernel_launch(void* const* d_in, const int* in_sizes, int n_in,
                              void* d_out, int out_size) {
    const float* X   = (const float*)d_in[0];
    const int*   ei  = (const int*)d_in[1];
    const float* W1  = (const float*)d_in[2];
    const float* b1  = (const float*)d_in[3];
    const float* W2  = (const float*)d_in[4];
    const float* b2  = (const float*)d_in[5];
    float*       out = (float*)d_out;

    cudaFuncSetAttribute(gemm1_mma, cudaFuncAttributeMaxDynamicSharedMemorySize,
                         SMEM_G1_BYTES);

    const int TB = 256;
    const int nodeGrid = (N_NODES + TB - 1) / TB;
    const int edgeGrid = (N_EDGES + TB - 1) / TB;
    const int convGrid = (F_IN * HID + TB - 1) / TB;
    const bool fork = g_s2 && g_e0 && g_e2;

    // convw first (gemm1's only dependency besides X)
    k_convw<<<convGrid, TB>>>(W1, W2);

    // fork: GEMM1 on side stream immediately — independent of the degree chain
    if (fork) {
        cudaEventRecord(g_e0, 0);
        cudaStreamWaitEvent(g_s2, g_e0, 0);
        gemm1_mma<<<(N_NODES + BM - 1) / BM, 256, SMEM_G1_BYTES, g_s2>>>(X);
        cudaEventRecord(g_e2, g_s2);
    } else {
        gemm1_mma<<<(N_NODES + BM - 1) / BM, 256, SMEM_G1_BYTES>>>(X);
    }

    // degree + CSR chain on main stream (runs under gemm1)
    k_zero_cnt   <<<nodeGrid, TB>>>(ei);
    k_cnt_scatter<<<edgeGrid, TB>>>(ei);
    k_scan1      <<<N_SBLK, SCAN_B>>>();
    k_scan2      <<<1, 256>>>();
    k_scan3      <<<nodeGrid, TB>>>();
    k_fill       <<<edgeGrid, TB>>>(ei);

    if (fork) cudaStreamWaitEvent(0, g_e2, 0);   // join before agg1

    k_agg1   <<<(N_NODES * 32 + TB - 1) / TB, TB>>>(b1);
    gemm2_mma<<<(N_NODES + 127) / 128, 256>>>();
    k_agg2   <<<(N_NODES * 32 + TB - 1) / TB, TB>>>(b2, out);
}

// round 12
// speedup vs baseline: 1.9612x; 1.0792x over previous
#include <cuda_runtime.h>
#include <cuda_bf16.h>
#include <cuda_fp16.h>
#include <cstdint>

#define N_NODES 100000
#define N_EDGES 800000
#define F_IN    256
#define HID     128
#define CLS     32
#define SCAN_B  512
#define N_SBLK  ((N_NODES + SCAN_B - 1) / SCAN_B)   // 196

// ---------------- scratch (device globals: no allocation allowed) ----------
__device__ int    g_cnt[N_NODES];
__device__ float  g_dinv[N_NODES];
__device__ int    g_rowptr[N_NODES + 1];
__device__ int    g_cursor[N_NODES];
__device__ int    g_col[N_EDGES];
__device__ int    g_bsum[N_SBLK];
__device__ int    g_boff[N_SBLK];
__device__ __half g_q1h[(size_t)N_NODES * HID];   // raw xw1 in fp16 (halved gather)
__device__ float  g_h1 [(size_t)N_NODES * HID];
__device__ float  g_q2 [(size_t)N_NODES * CLS];   // xw2 * dinv[row]
__device__ __nv_bfloat16 g_w1h[F_IN * HID];
__device__ __nv_bfloat16 g_w1l[F_IN * HID];
__device__ __nv_bfloat16 g_w2h[HID * CLS];
__device__ __nv_bfloat16 g_w2l[HID * CLS];
__device__ int    g_is64;

// ---------------- stream/events for fork-join overlap (created at load) -----
static cudaStream_t g_s2 = nullptr;
static cudaEvent_t  g_e0 = nullptr, g_e2 = nullptr;
namespace {
struct HxStreamInit {
    HxStreamInit() {
        cudaStreamCreateWithFlags(&g_s2, cudaStreamNonBlocking);
        cudaEventCreateWithFlags(&g_e0, cudaEventDisableTiming);
        cudaEventCreateWithFlags(&g_e2, cudaEventDisableTiming);
    }
};
static HxStreamInit g_hx_stream_init;
}

// ---------------- helpers ----------------------------------------------------
__device__ __forceinline__ uint32_t smem_addr(const void* p) {
    return (uint32_t)__cvta_generic_to_shared(p);
}
#define LDSM_X4(r, a)                                                          \
    asm volatile("ldmatrix.sync.aligned.m8n8.x4.shared.b16 {%0,%1,%2,%3}, [%4];" \
                 : "=r"((r)[0]), "=r"((r)[1]), "=r"((r)[2]), "=r"((r)[3])      \
                 : "r"(a))
#define LDSM_X2T(r, a)                                                         \
    asm volatile("ldmatrix.sync.aligned.m8n8.x2.trans.shared.b16 {%0,%1}, [%2];" \
                 : "=r"((r)[0]), "=r"((r)[1]) : "r"(a))
#define MMA_BF16(c, a, b)                                                      \
    asm volatile("mma.sync.aligned.m16n8k16.row.col.f32.bf16.bf16.f32 "        \
                 "{%0,%1,%2,%3}, {%4,%5,%6,%7}, {%8,%9}, {%0,%1,%2,%3};"       \
                 : "+f"((c)[0]), "+f"((c)[1]), "+f"((c)[2]), "+f"((c)[3])      \
                 : "r"((a)[0]), "r"((a)[1]), "r"((a)[2]), "r"((a)[3]),         \
                   "r"((b)[0]), "r"((b)[1]))

__device__ __forceinline__ int edge_at(const int* __restrict__ ei,
                                       int which, int e, int is64) {
    size_t base = (size_t)which * N_EDGES + (size_t)e;
    return is64 ? ei[base * 2] : ei[base];
}
__device__ __forceinline__ uint32_t pack_bf2(float a, float b) {
    __nv_bfloat162 p = make_bfloat162(__float2bfloat16(a), __float2bfloat16(b));
    return *(uint32_t*)&p;
}

// ---------------- weight conversion (hi/lo bf16 split) ----------------------
__global__ void k_convw(const float* __restrict__ W1,
                        const float* __restrict__ W2) {
    int i = blockIdx.x * blockDim.x + threadIdx.x;
    if (i < F_IN * HID) {
        float x = W1[i];
        __nv_bfloat16 h = __float2bfloat16(x);
        g_w1h[i] = h;
        g_w1l[i] = __float2bfloat16(x - __bfloat162float(h));
    }
    if (i < HID * CLS) {
        float x = W2[i];
        __nv_bfloat16 h = __float2bfloat16(x);
        g_w2h[i] = h;
        g_w2l[i] = __float2bfloat16(x - __bfloat162float(h));
    }
}

// ---------------- degree count (+ dtype probe fused) ------------------------
__global__ void k_zero_cnt(const int* __restrict__ ei) {
    int i = blockIdx.x * blockDim.x + threadIdx.x;
    if (i < N_NODES) g_cnt[i] = 0;
    if (i == 0) {
        int is64 = 1;
        for (int j = 0; j < 64; j++)
            if (ei[2 * j + 1] != 0) { is64 = 0; break; }
        g_is64 = is64;
    }
}
__global__ void k_cnt_scatter(const int* __restrict__ ei) {
    int e = blockIdx.x * blockDim.x + threadIdx.x;
    if (e >= N_EDGES) return;
    atomicAdd(&g_cnt[edge_at(ei, 1, e, g_is64)], 1);
}

// ---------------- CSR build: 3-phase scan (+dinv fused) + fill --------------
__global__ void k_scan1() {
    __shared__ int sh[SCAN_B];
    int t = threadIdx.x;
    int i = blockIdx.x * SCAN_B + t;
    int v = (i < N_NODES) ? g_cnt[i] : 0;
    sh[t] = v;
    __syncthreads();
#pragma unroll
    for (int off = 1; off < SCAN_B; off <<= 1) {
        int x = (t >= off) ? sh[t - off] : 0;
        __syncthreads();
        sh[t] += x;
        __syncthreads();
    }
    if (i < N_NODES) g_rowptr[i] = sh[t] - v;
    if (t == SCAN_B - 1) g_bsum[blockIdx.x] = sh[t];
}
__global__ void k_scan2() {
    __shared__ int sh[256];
    int t = threadIdx.x;
    int v = (t < N_SBLK) ? g_bsum[t] : 0;
    sh[t] = v;
    __syncthreads();
#pragma unroll
    for (int off = 1; off < 256; off <<= 1) {
        int x = (t >= off) ? sh[t - off] : 0;
        __syncthreads();
        sh[t] += x;
        __syncthreads();
    }
    if (t < N_SBLK) g_boff[t] = sh[t] - v;
}
__global__ void k_scan3() {
    int i = blockIdx.x * blockDim.x + threadIdx.x;
    if (i < N_NODES) {
        int rp = g_rowptr[i] + g_boff[i / SCAN_B];
        g_rowptr[i] = rp;
        g_cursor[i] = rp;
        g_dinv[i]   = rsqrtf((float)(g_cnt[i] + 1));   // +1 self loop
    }
    if (i == 0) g_rowptr[N_NODES] = N_EDGES;
}
__global__ void k_fill(const int* __restrict__ ei) {
    int e = blockIdx.x * blockDim.x + threadIdx.x;
    if (e >= N_EDGES) return;
    int is64 = g_is64;
    int s = edge_at(ei, 0, e, is64);
    int d = edge_at(ei, 1, e, is64);
    int pos = atomicAdd(&g_cursor[d], 1);
    g_col[pos] = s;
}

// ---------------- layer-1 GEMM: pipelined bf16-split mma --------------------
// q1h = fp16(X @ W1)   (raw, no dinv; fp16 storage halves agg1 gather bytes)
#define BM 64
#define BK 32
#define NKC (F_IN / BK)        // 8
#define A_STR 40
#define B_STR 136
#define A_BUF (BM * A_STR)
#define B_BUF (BK * B_STR)
#define OFF_AH 0
#define OFF_AL (2 * A_BUF)
#define OFF_BH (4 * A_BUF)
#define OFF_BL (4 * A_BUF + 2 * B_BUF)
#define SMEM_G1_ELEMS (4 * A_BUF + 4 * B_BUF)
#define SMEM_G1_BYTES (SMEM_G1_ELEMS * 2)       // 55296

__global__ __launch_bounds__(256, 2) void gemm1_mma(const float* __restrict__ X) {
    extern __shared__ __align__(16) char dsm_raw[];
    __nv_bfloat16* sm = (__nv_bfloat16*)dsm_raw;

    const int tid  = threadIdx.x;
    const int lane = tid & 31;
    const int wid  = tid >> 5;
    const int wm   = wid >> 2;
    const int wn   = wid & 3;
    const int rowBase = blockIdx.x * BM;

    const int a_r0 = tid >> 3,  a_c4 = (tid & 7) * 4;
    const int b_k0 = tid >> 4,  b_n8 = (tid & 15) * 8;

    float4 stA[2];
    uint4  stBh[2], stBl[2];

    float acc[2][4][4];
#pragma unroll
    for (int mi = 0; mi < 2; mi++)
#pragma unroll
        for (int ni = 0; ni < 4; ni++)
#pragma unroll
            for (int r = 0; r < 4; r++) acc[mi][ni][r] = 0.f;

    auto load_stage = [&](int kt) {
#pragma unroll
        for (int i = 0; i < 2; i++) {
            int gr = rowBase + a_r0 + i * 32;
            stA[i] = make_float4(0.f, 0.f, 0.f, 0.f);
            if (gr < N_NODES)
                stA[i] = *(const float4*)(X + (size_t)gr * F_IN + kt + a_c4);
        }
#pragma unroll
        for (int i = 0; i < 2; i++) {
            size_t off = (size_t)(kt + b_k0 + i * 16) * HID + b_n8;
            stBh[i] = *(const uint4*)(g_w1h + off);
            stBl[i] = *(const uint4*)(g_w1l + off);
        }
    };
    auto store_stage = [&](int buf) {
#pragma unroll
        for (int i = 0; i < 2; i++) {
            int r = a_r0 + i * 32;
            float4 v = stA[i];
            uint2 hh, ll;
            hh.x = pack_bf2(v.x, v.y); hh.y = pack_bf2(v.z, v.w);
            float lx = v.x - __bfloat162float(__float2bfloat16(v.x));
            float ly = v.y - __bfloat162float(__float2bfloat16(v.y));
            float lz = v.z - __bfloat162float(__float2bfloat16(v.z));
            float lw = v.w - __bfloat162float(__float2bfloat16(v.w));
            ll.x = pack_bf2(lx, ly); ll.y = pack_bf2(lz, lw);
            int idx = buf * A_BUF + r * A_STR + a_c4;
            *(uint2*)&sm[OFF_AH + idx] = hh;
            *(uint2*)&sm[OFF_AL + idx] = ll;
        }
#pragma unroll
        for (int i = 0; i < 2; i++) {
            int k = b_k0 + i * 16;
            int idx = buf * B_BUF + k * B_STR + b_n8;
            *(uint4*)&sm[OFF_BH + idx] = stBh[i];
            *(uint4*)&sm[OFF_BL + idx] = stBl[i];
        }
    };

    load_stage(0);
    store_stage(0);
    __syncthreads();

    for (int kc = 0; kc < NKC; kc++) {
        int buf = kc & 1;
        if (kc + 1 < NKC) load_stage((kc + 1) * BK);

#pragma unroll
        for (int ks = 0; ks < 2; ks++) {
            int k16 = ks * 16;
            uint32_t ah[2][4], al[2][4], bh[4][2], bl[4][2];
#pragma unroll
            for (int mi = 0; mi < 2; mi++) {
                int row = wm * 32 + mi * 16 + (lane & 15);
                int col = k16 + (lane >> 4) * 8;
                int idx = buf * A_BUF + row * A_STR + col;
                LDSM_X4(ah[mi], smem_addr(&sm[OFF_AH + idx]));
                LDSM_X4(al[mi], smem_addr(&sm[OFF_AL + idx]));
            }
#pragma unroll
            for (int ni = 0; ni < 4; ni++) {
                int krow = k16 + (lane & 15);
                int col  = wn * 32 + ni * 8;
                int idx = buf * B_BUF + krow * B_STR + col;
                LDSM_X2T(bh[ni], smem_addr(&sm[OFF_BH + idx]));
                LDSM_X2T(bl[ni], smem_addr(&sm[OFF_BL + idx]));
            }
#pragma unroll
            for (int mi = 0; mi < 2; mi++)
#pragma unroll
                for (int ni = 0; ni < 4; ni++) {
                    MMA_BF16(acc[mi][ni], ah[mi], bh[ni]);
                    MMA_BF16(acc[mi][ni], ah[mi], bl[ni]);
                    MMA_BF16(acc[mi][ni], al[mi], bh[ni]);
                }
        }
        if (kc + 1 < NKC) store_stage(buf ^ 1);
        __syncthreads();
    }

    // epilogue: fp16 store (adjacent col pairs -> one half2 per fragment reg pair)
    const int rBase = rowBase + wm * 32 + (lane >> 2);
    const int cBase = wn * 32 + (lane & 3) * 2;
#pragma unroll
    for (int mi = 0; mi < 2; mi++) {
        int gr0 = rBase + mi * 16;
        int gr1 = gr0 + 8;
#pragma unroll
        for (int ni = 0; ni < 4; ni++) {
            int gc = cBase + ni * 8;
            if (gr0 < N_NODES)
                *(__half2*)(g_q1h + (size_t)gr0 * HID + gc) =
                    __floats2half2_rn(acc[mi][ni][0], acc[mi][ni][1]);
            if (gr1 < N_NODES)
                *(__half2*)(g_q1h + (size_t)gr1 * HID + gc) =
                    __floats2half2_rn(acc[mi][ni][2], acc[mi][ni][3]);
        }
    }
}

// ---------------- CSR aggregation layer 1 (fp16 gather, fp32 accumulate) ----
// h1[i] = relu(dinv[i] * sum_{s in {i} U nbrs} q1h[s]*dinv[s] + b1)
__global__ void k_agg1(const float* __restrict__ b1) {
    int node = blockIdx.x * (blockDim.x >> 5) + (threadIdx.x >> 5);
    int lane = threadIdx.x & 31;
    if (node >= N_NODES) return;
    int start = g_rowptr[node];
    int deg   = g_rowptr[node + 1] - start;
    float d = g_dinv[node];

    const uint2* q1v = (const uint2*)g_q1h;   // 32 uint2 (4 halves each) per row

    auto gacc = [&](int s, float ds, float4& a) {
        uint2 u = q1v[(size_t)s * 32 + lane];
        float2 p0 = __half22float2(*(__half2*)&u.x);
        float2 p1 = __half22float2(*(__half2*)&u.y);
        a.x += p0.x * ds; a.y += p0.y * ds;
        a.z += p1.x * ds; a.w += p1.y * ds;
    };

    float4 acc = make_float4(0.f, 0.f, 0.f, 0.f);
    gacc(node, d, acc);                          // self term

    int myidx = (lane < deg) ? g_col[start + lane] : 0;
    int n32 = deg < 32 ? deg : 32;
    int e = 0;
    for (; e + 4 <= n32; e += 4) {
        int s0 = __shfl_sync(0xffffffffu, myidx, e);
        int s1 = __shfl_sync(0xffffffffu, myidx, e + 1);
        int s2 = __shfl_sync(0xffffffffu, myidx, e + 2);
        int s3 = __shfl_sync(0xffffffffu, myidx, e + 3);
        float d0 = g_dinv[s0], d1 = g_dinv[s1], d2 = g_dinv[s2], d3 = g_dinv[s3];
        uint2 u0 = q1v[(size_t)s0 * 32 + lane];
        uint2 u1 = q1v[(size_t)s1 * 32 + lane];
        uint2 u2 = q1v[(size_t)s2 * 32 + lane];
        uint2 u3 = q1v[(size_t)s3 * 32 + lane];
        float2 a0 = __half22float2(*(__half2*)&u0.x), b0 = __half22float2(*(__half2*)&u0.y);
        float2 a1 = __half22float2(*(__half2*)&u1.x), b1f = __half22float2(*(__half2*)&u1.y);
        float2 a2 = __half22float2(*(__half2*)&u2.x), b2f = __half22float2(*(__half2*)&u2.y);
        float2 a3 = __half22float2(*(__half2*)&u3.x), b3f = __half22float2(*(__half2*)&u3.y);
        acc.x += (a0.x * d0 + a1.x * d1) + (a2.x * d2 + a3.x * d3);
        acc.y += (a0.y * d0 + a1.y * d1) + (a2.y * d2 + a3.y * d3);
        acc.z += (b0.x * d0 + b1f.x * d1) + (b2f.x * d2 + b3f.x * d3);
        acc.w += (b0.y * d0 + b1f.y * d1) + (b2f.y * d2 + b3f.y * d3);
    }
    for (; e < n32; e++) {
        int s = __shfl_sync(0xffffffffu, myidx, e);
        gacc(s, g_dinv[s], acc);
    }
    for (e = 32; e < deg; e++) {
        int s = g_col[start + e];
        gacc(s, g_dinv[s], acc);
    }

    float4 b = ((const float4*)b1)[lane];
    float4 o;
    o.x = fmaxf(fmaf(acc.x, d, b.x), 0.f);
    o.y = fmaxf(fmaf(acc.y, d, b.y), 0.f);
    o.z = fmaxf(fmaf(acc.z, d, b.z), 0.f);
    o.w = fmaxf(fmaf(acc.w, d, b.w), 0.f);
    ((float4*)(g_h1 + (size_t)node * HID))[lane] = o;
}

// ---------------- layer-2 GEMM: bf16-split mma, precomputed W2 --------------
// q2 = (h1 @ W2) * dinv[row];  M tiles of 128, N=32, K=128
#define APAD 8
#define BPAD 8
__global__ __launch_bounds__(256, 2) void gemm2_mma() {
    __shared__ __align__(16) __nv_bfloat16 sAh[128][BK + APAD];
    __shared__ __align__(16) __nv_bfloat16 sAl[128][BK + APAD];
    __shared__ __align__(16) __nv_bfloat16 sBh[BK][CLS + BPAD];
    __shared__ __align__(16) __nv_bfloat16 sBl[BK][CLS + BPAD];

    const int tid  = threadIdx.x;
    const int lane = tid & 31;
    const int wid  = tid >> 5;
    const int rowBase = blockIdx.x * 128;

    float acc[4][4];
#pragma unroll
    for (int ni = 0; ni < 4; ni++)
#pragma unroll
        for (int r = 0; r < 4; r++) acc[ni][r] = 0.f;

    for (int kt = 0; kt < HID; kt += BK) {
#pragma unroll
        for (int i = 0; i < 4; i++) {
            int idx = tid + i * 256;
            int r = idx >> 3, c4 = (idx & 7) * 4;
            int gr = rowBase + r;
            float4 v = make_float4(0.f, 0.f, 0.f, 0.f);
            if (gr < N_NODES)
                v = *(const float4*)(g_h1 + (size_t)gr * HID + kt + c4);
            uint2 hh, ll;
            hh.x = pack_bf2(v.x, v.y); hh.y = pack_bf2(v.z, v.w);
            float lx = v.x - __bfloat162float(__float2bfloat16(v.x));
            float ly = v.y - __bfloat162float(__float2bfloat16(v.y));
            float lz = v.z - __bfloat162float(__float2bfloat16(v.z));
            float lw = v.w - __bfloat162float(__float2bfloat16(v.w));
            ll.x = pack_bf2(lx, ly); ll.y = pack_bf2(lz, lw);
            *(uint2*)&sAh[r][c4] = hh;
            *(uint2*)&sAl[r][c4] = ll;
        }
        if (tid < 128) {
            int k = tid >> 2, n8 = (tid & 3) * 8;
            size_t off = (size_t)(kt + k) * CLS + n8;
            *(uint4*)&sBh[k][n8] = *(const uint4*)(g_w2h + off);
            *(uint4*)&sBl[k][n8] = *(const uint4*)(g_w2l + off);
        }
        __syncthreads();

#pragma unroll
        for (int ks = 0; ks < BK / 16; ks++) {
            int k16 = ks * 16;
            uint32_t ah[4], al[4], bh[4][2], bl[4][2];
            {
                int row = wid * 16 + (lane & 15);
                int col = k16 + (lane >> 4) * 8;
                LDSM_X4(ah, smem_addr(&sAh[row][col]));
                LDSM_X4(al, smem_addr(&sAl[row][col]));
            }
#pragma unroll
            for (int ni = 0; ni < 4; ni++) {
                int krow = k16 + (lane & 15);
                int col  = ni * 8;
                LDSM_X2T(bh[ni], smem_addr(&sBh[krow][col]));
                LDSM_X2T(bl[ni], smem_addr(&sBl[krow][col]));
            }
#pragma unroll
            for (int ni = 0; ni < 4; ni++) {
                MMA_BF16(acc[ni], ah, bh[ni]);
                MMA_BF16(acc[ni], ah, bl[ni]);
                MMA_BF16(acc[ni], al, bh[ni]);
            }
        }
        __syncthreads();
    }

    const int r0 = rowBase + wid * 16 + (lane >> 2);
    const int r1 = r0 + 8;
    const int cBase = (lane & 3) * 2;
    float d0 = (r0 < N_NODES) ? g_dinv[r0] : 0.f;
    float d1 = (r1 < N_NODES) ? g_dinv[r1] : 0.f;
#pragma unroll
    for (int ni = 0; ni < 4; ni++) {
        int gc = cBase + ni * 8;
        if (r0 < N_NODES)
            *(float2*)(g_q2 + (size_t)r0 * CLS + gc) =
                make_float2(acc[ni][0] * d0, acc[ni][1] * d0);
        if (r1 < N_NODES)
            *(float2*)(g_q2 + (size_t)r1 * CLS + gc) =
                make_float2(acc[ni][2] * d1, acc[ni][3] * d1);
    }
}

// ---------------- CSR aggregation layer 2 (fused bias+logsoftmax) -----------
__global__ void k_agg2(const float* __restrict__ b2,
                       float* __restrict__ out) {
    int node = blockIdx.x * (blockDim.x >> 5) + (threadIdx.x >> 5);
    int lane = threadIdx.x & 31;
    if (node >= N_NODES) return;
    int start = g_rowptr[node];
    int deg   = g_rowptr[node + 1] - start;

    float acc = g_q2[(size_t)node * CLS + lane];     // self term

    int myidx = (lane < deg) ? g_col[start + lane] : 0;
    int n32 = deg < 32 ? deg : 32;
    int e = 0;
    for (; e + 4 <= n32; e += 4) {
        int s0 = __shfl_sync(0xffffffffu, myidx, e);
        int s1 = __shfl_sync(0xffffffffu, myidx, e + 1);
        int s2 = __shfl_sync(0xffffffffu, myidx, e + 2);
        int s3 = __shfl_sync(0xffffffffu, myidx, e + 3);
        float v0 = g_q2[(size_t)s0 * CLS + lane];
        float v1 = g_q2[(size_t)s1 * CLS + lane];
        float v2 = g_q2[(size_t)s2 * CLS + lane];
        float v3 = g_q2[(size_t)s3 * CLS + lane];
        acc += (v0 + v1) + (v2 + v3);
    }
    for (; e < n32; e++) {
        int s = __shfl_sync(0xffffffffu, myidx, e);
        acc += g_q2[(size_t)s * CLS + lane];
    }
    for (e = 32; e < deg; e++)
        acc += g_q2[(size_t)g_col[start + e] * CLS + lane];

    float v = fmaf(acc, g_dinv[node], b2[lane]);
    float m = v;
#pragma unroll
    for (int o = 16; o > 0; o >>= 1) m = fmaxf(m, __shfl_xor_sync(0xffffffffu, m, o));
    float ex = __expf(v - m);
    float ssum = ex;
#pragma unroll
    for (int o = 16; o > 0; o >>= 1) ssum += __shfl_xor_sync(0xffffffffu, ssum, o);
    out[(size_t)node * CLS + lane] = v - m - __logf(ssum);
}

// ---------------- launch -----------------------------------------------------
extern "C" void kernel_launch(void* const* d_in, const int* in_sizes, int n_in,
                              void* d_out, int out_size) {
    const float* X   = (const float*)d_in[0];
    const int*   ei  = (const int*)d_in[1];
    const float* W1  = (const float*)d_in[2];
    const float* b1  = (const float*)d_in[3];
    const float* W2  = (const float*)d_in[4];
    const float* b2  = (const float*)d_in[5];
    float*       out = (float*)d_out;

    cudaFuncSetAttribute(gemm1_mma, cudaFuncAttributeMaxDynamicSharedMemorySize,
                         SMEM_G1_BYTES);

    const int TB = 256;
    const int nodeGrid = (N_NODES + TB - 1) / TB;
    const int edgeGrid = (N_EDGES + TB - 1) / TB;
    const int convGrid = (F_IN * HID + TB - 1) / TB;
    const bool fork = g_s2 && g_e0 && g_e2;

    k_convw<<<convGrid, TB>>>(W1, W2);

    // fork: GEMM1 on side stream — independent of the degree chain
    if (fork) {
        cudaEventRecord(g_e0, 0);
        cudaStreamWaitEvent(g_s2, g_e0, 0);
        gemm1_mma<<<(N_NODES + BM - 1) / BM, 256, SMEM_G1_BYTES, g_s2>>>(X);
        cudaEventRecord(g_e2, g_s2);
    } else {
        gemm1_mma<<<(N_NODES + BM - 1) / BM, 256, SMEM_G1_BYTES>>>(X);
    }

    // degree + CSR chain on main stream (hidden under gemm1)
    k_zero_cnt   <<<nodeGrid, TB>>>(ei);
    k_cnt_scatter<<<edgeGrid, TB>>>(ei);
    k_scan1      <<<N_SBLK, SCAN_B>>>();
    k_scan2      <<<1, 256>>>();
    k_scan3      <<<nodeGrid, TB>>>();
    k_fill       <<<edgeGrid, TB>>>(ei);

    if (fork) cudaStreamWaitEvent(0, g_e2, 0);   // join before agg1

    k_agg1   <<<(N_NODES * 32 + TB - 1) / TB, TB>>>(b1);
    gemm2_mma<<<(N_NODES + 127) / 128, 256>>>();
    k_agg2   <<<(N_NODES * 32 + TB - 1) / TB, TB>>>(b2, out);
}

// round 13
// speedup vs baseline: 2.2181x; 1.1310x over previous
#include <cuda_runtime.h>
#include <cuda_fp16.h>
#include <cstdint>

#define N_NODES 100000
#define N_EDGES 800000
#define F_IN    256
#define HID     128
#define CLS     32
#define SCAN_B  512
#define N_SBLK  ((N_NODES + SCAN_B - 1) / SCAN_B)   // 196

// ---------------- scratch (device globals: no allocation allowed) ----------
__device__ int    g_cnt[N_NODES];
__device__ float  g_dinv[N_NODES];
__device__ int    g_rowptr[N_NODES + 1];
__device__ int    g_cursor[N_NODES];
__device__ int    g_col[N_EDGES];
__device__ int    g_bsum[N_SBLK];
__device__ int    g_boff[N_SBLK];
__device__ __half g_q1h[(size_t)N_NODES * HID];   // raw xw1, fp16
__device__ __half g_h1h[(size_t)N_NODES * HID];   // relu output, fp16
__device__ __half g_q2h[(size_t)N_NODES * CLS];   // xw2*dinv, fp16
__device__ __half g_w1h[F_IN * HID];              // W1 fp16 hi
__device__ __half g_w1l[F_IN * HID];              // W1 fp16 lo
__device__ __half g_w2h[HID * CLS];
__device__ __half g_w2l[HID * CLS];
__device__ int    g_is64;

// ---------------- stream/events for fork-join overlap (created at load) -----
static cudaStream_t g_s2 = nullptr;
static cudaEvent_t  g_e0 = nullptr, g_e2 = nullptr;
namespace {
struct HxStreamInit {
    HxStreamInit() {
        cudaStreamCreateWithFlags(&g_s2, cudaStreamNonBlocking);
        cudaEventCreateWithFlags(&g_e0, cudaEventDisableTiming);
        cudaEventCreateWithFlags(&g_e2, cudaEventDisableTiming);
    }
};
static HxStreamInit g_hx_stream_init;
}

// ---------------- helpers ----------------------------------------------------
__device__ __forceinline__ uint32_t smem_addr(const void* p) {
    return (uint32_t)__cvta_generic_to_shared(p);
}
#define LDSM_X4(r, a)                                                          \
    asm volatile("ldmatrix.sync.aligned.m8n8.x4.shared.b16 {%0,%1,%2,%3}, [%4];" \
                 : "=r"((r)[0]), "=r"((r)[1]), "=r"((r)[2]), "=r"((r)[3])      \
                 : "r"(a))
#define LDSM_X2T(r, a)                                                         \
    asm volatile("ldmatrix.sync.aligned.m8n8.x2.trans.shared.b16 {%0,%1}, [%2];" \
                 : "=r"((r)[0]), "=r"((r)[1]) : "r"(a))
#define MMA_F16(c, a, b)                                                       \
    asm volatile("mma.sync.aligned.m16n8k16.row.col.f32.f16.f16.f32 "          \
                 "{%0,%1,%2,%3}, {%4,%5,%6,%7}, {%8,%9}, {%0,%1,%2,%3};"       \
                 : "+f"((c)[0]), "+f"((c)[1]), "+f"((c)[2]), "+f"((c)[3])      \
                 : "r"((a)[0]), "r"((a)[1]), "r"((a)[2]), "r"((a)[3]),         \
                   "r"((b)[0]), "r"((b)[1]))
#define CP_ASYNC16(dst, src, sz)                                               \
    asm volatile("cp.async.ca.shared.global [%0], [%1], 16, %2;"               \
                 :: "r"(dst), "l"(src), "r"(sz) : "memory")
#define CP_COMMIT() asm volatile("cp.async.commit_group;" ::: "memory")
#define CP_WAIT0()  asm volatile("cp.async.wait_group 0;" ::: "memory")

__device__ __forceinline__ int edge_at(const int* __restrict__ ei,
                                       int which, int e, int is64) {
    size_t base = (size_t)which * N_EDGES + (size_t)e;
    return is64 ? ei[base * 2] : ei[base];
}

// ---------------- weight conversion (hi/lo fp16 split) ----------------------
__global__ void k_convw(const float* __restrict__ W1,
                        const float* __restrict__ W2) {
    int i = blockIdx.x * blockDim.x + threadIdx.x;
    if (i < F_IN * HID) {
        float x = W1[i];
        __half h = __float2half_rn(x);
        g_w1h[i] = h;
        g_w1l[i] = __float2half_rn(x - __half2float(h));
    }
    if (i < HID * CLS) {
        float x = W2[i];
        __half h = __float2half_rn(x);
        g_w2h[i] = h;
        g_w2l[i] = __float2half_rn(x - __half2float(h));
    }
}

// ---------------- degree count (+ dtype probe fused) ------------------------
__global__ void k_zero_cnt(const int* __restrict__ ei) {
    int i = blockIdx.x * blockDim.x + threadIdx.x;
    if (i < N_NODES) g_cnt[i] = 0;
    if (i == 0) {
        int is64 = 1;
        for (int j = 0; j < 64; j++)
            if (ei[2 * j + 1] != 0) { is64 = 0; break; }
        g_is64 = is64;
    }
}
__global__ void k_cnt_scatter(const int* __restrict__ ei) {
    int e = blockIdx.x * blockDim.x + threadIdx.x;
    if (e >= N_EDGES) return;
    atomicAdd(&g_cnt[edge_at(ei, 1, e, g_is64)], 1);
}

// ---------------- CSR build: 3-phase scan (+dinv fused) + fill --------------
__global__ void k_scan1() {
    __shared__ int sh[SCAN_B];
    int t = threadIdx.x;
    int i = blockIdx.x * SCAN_B + t;
    int v = (i < N_NODES) ? g_cnt[i] : 0;
    sh[t] = v;
    __syncthreads();
#pragma unroll
    for (int off = 1; off < SCAN_B; off <<= 1) {
        int x = (t >= off) ? sh[t - off] : 0;
        __syncthreads();
        sh[t] += x;
        __syncthreads();
    }
    if (i < N_NODES) g_rowptr[i] = sh[t] - v;
    if (t == SCAN_B - 1) g_bsum[blockIdx.x] = sh[t];
}
__global__ void k_scan2() {
    __shared__ int sh[256];
    int t = threadIdx.x;
    int v = (t < N_SBLK) ? g_bsum[t] : 0;
    sh[t] = v;
    __syncthreads();
#pragma unroll
    for (int off = 1; off < 256; off <<= 1) {
        int x = (t >= off) ? sh[t - off] : 0;
        __syncthreads();
        sh[t] += x;
        __syncthreads();
    }
    if (t < N_SBLK) g_boff[t] = sh[t] - v;
}
__global__ void k_scan3() {
    int i = blockIdx.x * blockDim.x + threadIdx.x;
    if (i < N_NODES) {
        int rp = g_rowptr[i] + g_boff[i / SCAN_B];
        g_rowptr[i] = rp;
        g_cursor[i] = rp;
        g_dinv[i]   = rsqrtf((float)(g_cnt[i] + 1));   // +1 self loop
    }
    if (i == 0) g_rowptr[N_NODES] = N_EDGES;
}
__global__ void k_fill(const int* __restrict__ ei) {
    int e = blockIdx.x * blockDim.x + threadIdx.x;
    if (e >= N_EDGES) return;
    int is64 = g_is64;
    int s = edge_at(ei, 0, e, is64);
    int d = edge_at(ei, 1, e, is64);
    int pos = atomicAdd(&g_cursor[d], 1);
    g_col[pos] = s;
}

// ---------------- layer-1 GEMM: fp16 A + fp16-split W1, 2xMMA, cp.async -----
// q1h = fp16(X @ W1)
#define BM 64
#define BK 32
#define NKC (F_IN / BK)        // 8
#define A_STR 40               // halves
#define B_STR 136
#define A_BUF (BM * A_STR)     // 2560
#define B_BUF (BK * B_STR)     // 4352
#define OFF_A  0
#define OFF_BH (2 * A_BUF)
#define OFF_BL (2 * A_BUF + 2 * B_BUF)
#define SMEM_G1_ELEMS (2 * A_BUF + 4 * B_BUF)   // 22528 halves
#define SMEM_G1_BYTES (SMEM_G1_ELEMS * 2)       // 45056 B

__global__ __launch_bounds__(256, 2) void gemm1_mma(const float* __restrict__ X) {
    extern __shared__ __align__(16) char dsm_raw[];
    __half* sm = (__half*)dsm_raw;

    const int tid  = threadIdx.x;
    const int lane = tid & 31;
    const int wid  = tid >> 5;
    const int wm   = wid >> 2;       // 0..1 (32 rows)
    const int wn   = wid & 3;        // 0..3 (32 cols)
    const int rowBase = blockIdx.x * BM;

    const int a_r0 = tid >> 3,  a_c4 = (tid & 7) * 4;
    const int b_k0 = tid >> 4,  b_n8 = (tid & 15) * 8;

    float4 stA[2];

    float acc[2][4][4];
#pragma unroll
    for (int mi = 0; mi < 2; mi++)
#pragma unroll
        for (int ni = 0; ni < 4; ni++)
#pragma unroll
            for (int r = 0; r < 4; r++) acc[mi][ni][r] = 0.f;

    auto issue_B = [&](int kt, int buf) {
#pragma unroll
        for (int i = 0; i < 2; i++) {
            int k = b_k0 + i * 16;
            size_t off = (size_t)(kt + k) * HID + b_n8;
            CP_ASYNC16(smem_addr(&sm[OFF_BH + buf * B_BUF + k * B_STR + b_n8]),
                       g_w1h + off, 16);
            CP_ASYNC16(smem_addr(&sm[OFF_BL + buf * B_BUF + k * B_STR + b_n8]),
                       g_w1l + off, 16);
        }
        CP_COMMIT();
    };
    auto load_A = [&](int kt) {
#pragma unroll
        for (int i = 0; i < 2; i++) {
            int gr = rowBase + a_r0 + i * 32;
            stA[i] = make_float4(0.f, 0.f, 0.f, 0.f);
            if (gr < N_NODES)
                stA[i] = *(const float4*)(X + (size_t)gr * F_IN + kt + a_c4);
        }
    };
    auto store_A = [&](int buf) {
#pragma unroll
        for (int i = 0; i < 2; i++) {
            int r = a_r0 + i * 32;
            float4 v = stA[i];
            uint2 u;
            *(__half2*)&u.x = __floats2half2_rn(v.x, v.y);
            *(__half2*)&u.y = __floats2half2_rn(v.z, v.w);
            *(uint2*)&sm[OFF_A + buf * A_BUF + r * A_STR + a_c4] = u;
        }
    };

    issue_B(0, 0);
    load_A(0);
    store_A(0);
    CP_WAIT0();
    __syncthreads();

    for (int kc = 0; kc < NKC; kc++) {
        int buf = kc & 1;
        if (kc + 1 < NKC) {
            issue_B((kc + 1) * BK, buf ^ 1);
            load_A((kc + 1) * BK);
        }

#pragma unroll
        for (int ks = 0; ks < 2; ks++) {
            int k16 = ks * 16;
            uint32_t a[2][4], bh[4][2], bl[4][2];
#pragma unroll
            for (int mi = 0; mi < 2; mi++) {
                int row = wm * 32 + mi * 16 + (lane & 15);
                int col = k16 + (lane >> 4) * 8;
                LDSM_X4(a[mi], smem_addr(&sm[OFF_A + buf * A_BUF + row * A_STR + col]));
            }
#pragma unroll
            for (int ni = 0; ni < 4; ni++) {
                int krow = k16 + (lane & 15);
                int col  = wn * 32 + ni * 8;
                LDSM_X2T(bh[ni], smem_addr(&sm[OFF_BH + buf * B_BUF + krow * B_STR + col]));
                LDSM_X2T(bl[ni], smem_addr(&sm[OFF_BL + buf * B_BUF + krow * B_STR + col]));
            }
#pragma unroll
            for (int mi = 0; mi < 2; mi++)
#pragma unroll
                for (int ni = 0; ni < 4; ni++) {
                    MMA_F16(acc[mi][ni], a[mi], bh[ni]);
                    MMA_F16(acc[mi][ni], a[mi], bl[ni]);
                }
        }
        if (kc + 1 < NKC) store_A(buf ^ 1);
        CP_WAIT0();
        __syncthreads();
    }

    const int rBase = rowBase + wm * 32 + (lane >> 2);
    const int cBase = wn * 32 + (lane & 3) * 2;
#pragma unroll
    for (int mi = 0; mi < 2; mi++) {
        int gr0 = rBase + mi * 16;
        int gr1 = gr0 + 8;
#pragma unroll
        for (int ni = 0; ni < 4; ni++) {
            int gc = cBase + ni * 8;
            if (gr0 < N_NODES)
                *(__half2*)(g_q1h + (size_t)gr0 * HID + gc) =
                    __floats2half2_rn(acc[mi][ni][0], acc[mi][ni][1]);
            if (gr1 < N_NODES)
                *(__half2*)(g_q1h + (size_t)gr1 * HID + gc) =
                    __floats2half2_rn(acc[mi][ni][2], acc[mi][ni][3]);
        }
    }
}

// ---------------- CSR aggregation layer 1 (fp16 gather, fp16 h1 write) ------
__global__ void k_agg1(const float* __restrict__ b1) {
    int node = blockIdx.x * (blockDim.x >> 5) + (threadIdx.x >> 5);
    int lane = threadIdx.x & 31;
    if (node >= N_NODES) return;
    int start = g_rowptr[node];
    int deg   = g_rowptr[node + 1] - start;
    float d = g_dinv[node];

    const uint2* q1v = (const uint2*)g_q1h;

    auto gacc = [&](int s, float ds, float4& a) {
        uint2 u = q1v[(size_t)s * 32 + lane];
        float2 p0 = __half22float2(*(__half2*)&u.x);
        float2 p1 = __half22float2(*(__half2*)&u.y);
        a.x += p0.x * ds; a.y += p0.y * ds;
        a.z += p1.x * ds; a.w += p1.y * ds;
    };

    float4 acc = make_float4(0.f, 0.f, 0.f, 0.f);
    gacc(node, d, acc);                          // self term

    int myidx = (lane < deg) ? g_col[start + lane] : 0;
    int n32 = deg < 32 ? deg : 32;
    int e = 0;
    for (; e + 4 <= n32; e += 4) {
        int s0 = __shfl_sync(0xffffffffu, myidx, e);
        int s1 = __shfl_sync(0xffffffffu, myidx, e + 1);
        int s2 = __shfl_sync(0xffffffffu, myidx, e + 2);
        int s3 = __shfl_sync(0xffffffffu, myidx, e + 3);
        float d0 = g_dinv[s0], d1 = g_dinv[s1], d2 = g_dinv[s2], d3 = g_dinv[s3];
        uint2 u0 = q1v[(size_t)s0 * 32 + lane];
        uint2 u1 = q1v[(size_t)s1 * 32 + lane];
        uint2 u2 = q1v[(size_t)s2 * 32 + lane];
        uint2 u3 = q1v[(size_t)s3 * 32 + lane];
        float2 a0 = __half22float2(*(__half2*)&u0.x), c0 = __half22float2(*(__half2*)&u0.y);
        float2 a1 = __half22float2(*(__half2*)&u1.x), c1 = __half22float2(*(__half2*)&u1.y);
        float2 a2 = __half22float2(*(__half2*)&u2.x), c2 = __half22float2(*(__half2*)&u2.y);
        float2 a3 = __half22float2(*(__half2*)&u3.x), c3 = __half22float2(*(__half2*)&u3.y);
        acc.x += (a0.x * d0 + a1.x * d1) + (a2.x * d2 + a3.x * d3);
        acc.y += (a0.y * d0 + a1.y * d1) + (a2.y * d2 + a3.y * d3);
        acc.z += (c0.x * d0 + c1.x * d1) + (c2.x * d2 + c3.x * d3);
        acc.w += (c0.y * d0 + c1.y * d1) + (c2.y * d2 + c3.y * d3);
    }
    for (; e < n32; e++) {
        int s = __shfl_sync(0xffffffffu, myidx, e);
        gacc(s, g_dinv[s], acc);
    }
    for (e = 32; e < deg; e++) {
        int s = g_col[start + e];
        gacc(s, g_dinv[s], acc);
    }

    float4 b = ((const float4*)b1)[lane];
    float4 o;
    o.x = fmaxf(fmaf(acc.x, d, b.x), 0.f);
    o.y = fmaxf(fmaf(acc.y, d, b.y), 0.f);
    o.z = fmaxf(fmaf(acc.z, d, b.z), 0.f);
    o.w = fmaxf(fmaf(acc.w, d, b.w), 0.f);
    uint2 u;
    *(__half2*)&u.x = __floats2half2_rn(o.x, o.y);
    *(__half2*)&u.y = __floats2half2_rn(o.z, o.w);
    ((uint2*)(g_h1h + (size_t)node * HID))[lane] = u;
}

// ---------------- layer-2 GEMM: fp16 A (h1 direct) + fp16-split W2, 2xMMA ---
// q2h = fp16((h1 @ W2) * dinv[row]);  M tile 128, N=32, K=128
#define A2_STR 40
#define B2_STR 40
__global__ __launch_bounds__(256, 2) void gemm2_mma() {
    __shared__ __align__(16) __half sA [128][A2_STR];
    __shared__ __align__(16) __half sBh[BK][B2_STR];
    __shared__ __align__(16) __half sBl[BK][B2_STR];

    const int tid  = threadIdx.x;
    const int lane = tid & 31;
    const int wid  = tid >> 5;
    const int rowBase = blockIdx.x * 128;

    float acc[4][4];
#pragma unroll
    for (int ni = 0; ni < 4; ni++)
#pragma unroll
        for (int r = 0; r < 4; r++) acc[ni][r] = 0.f;

    for (int kt = 0; kt < HID; kt += BK) {
        // A tile: h1h[rowBase..+128, kt..+32) via cp.async (512 16B chunks)
#pragma unroll
        for (int i = 0; i < 2; i++) {
            int idx = tid + i * 256;
            int r = idx >> 2, c8 = (idx & 3) * 8;
            int gr = rowBase + r;
            int ok = (gr < N_NODES);
            const __half* src = g_h1h + (size_t)(ok ? gr : 0) * HID + kt + c8;
            CP_ASYNC16(smem_addr(&sA[r][c8]), src, ok ? 16 : 0);
        }
        // B tiles: W2 hi (threads 0-127), lo (threads 128-255)
        {
            int t = tid & 127;
            int r = t >> 2, c8 = (t & 3) * 8;
            size_t off = (size_t)(kt + r) * CLS + c8;
            if (tid < 128) CP_ASYNC16(smem_addr(&sBh[r][c8]), g_w2h + off, 16);
            else           CP_ASYNC16(smem_addr(&sBl[r][c8]), g_w2l + off, 16);
        }
        CP_COMMIT();
        CP_WAIT0();
        __syncthreads();

#pragma unroll
        for (int ks = 0; ks < 2; ks++) {
            int k16 = ks * 16;
            uint32_t a[4], bh[4][2], bl[4][2];
            {
                int row = wid * 16 + (lane & 15);
                int col = k16 + (lane >> 4) * 8;
                LDSM_X4(a, smem_addr(&sA[row][col]));
            }
#pragma unroll
            for (int ni = 0; ni < 4; ni++) {
                int krow = k16 + (lane & 15);
                int col  = ni * 8;
                LDSM_X2T(bh[ni], smem_addr(&sBh[krow][col]));
                LDSM_X2T(bl[ni], smem_addr(&sBl[krow][col]));
            }
#pragma unroll
            for (int ni = 0; ni < 4; ni++) {
                MMA_F16(acc[ni], a, bh[ni]);
                MMA_F16(acc[ni], a, bl[ni]);
            }
        }
        __syncthreads();
    }

    const int r0 = rowBase + wid * 16 + (lane >> 2);
    const int r1 = r0 + 8;
    const int cBase = (lane & 3) * 2;
    float d0 = (r0 < N_NODES) ? g_dinv[r0] : 0.f;
    float d1 = (r1 < N_NODES) ? g_dinv[r1] : 0.f;
#pragma unroll
    for (int ni = 0; ni < 4; ni++) {
        int gc = cBase + ni * 8;
        if (r0 < N_NODES)
            *(__half2*)(g_q2h + (size_t)r0 * CLS + gc) =
                __floats2half2_rn(acc[ni][0] * d0, acc[ni][1] * d0);
        if (r1 < N_NODES)
            *(__half2*)(g_q2h + (size_t)r1 * CLS + gc) =
                __floats2half2_rn(acc[ni][2] * d1, acc[ni][3] * d1);
    }
}

// ---------------- CSR aggregation layer 2 (fp16 gather, bias+logsoftmax) ----
__global__ void k_agg2(const float* __restrict__ b2,
                       float* __restrict__ out) {
    int node = blockIdx.x * (blockDim.x >> 5) + (threadIdx.x >> 5);
    int lane = threadIdx.x & 31;
    if (node >= N_NODES) return;
    int start = g_rowptr[node];
    int deg   = g_rowptr[node + 1] - start;

    float acc = __half2float(g_q2h[(size_t)node * CLS + lane]);   // self term

    int myidx = (lane < deg) ? g_col[start + lane] : 0;
    int n32 = deg < 32 ? deg : 32;
    int e = 0;
    for (; e + 4 <= n32; e += 4) {
        int s0 = __shfl_sync(0xffffffffu, myidx, e);
        int s1 = __shfl_sync(0xffffffffu, myidx, e + 1);
        int s2 = __shfl_sync(0xffffffffu, myidx, e + 2);
        int s3 = __shfl_sync(0xffffffffu, myidx, e + 3);
        float v0 = __half2float(g_q2h[(size_t)s0 * CLS + lane]);
        float v1 = __half2float(g_q2h[(size_t)s1 * CLS + lane]);
        float v2 = __half2float(g_q2h[(size_t)s2 * CLS + lane]);
        float v3 = __half2float(g_q2h[(size_t)s3 * CLS + lane]);
        acc += (v0 + v1) + (v2 + v3);
    }
    for (; e < n32; e++) {
        int s = __shfl_sync(0xffffffffu, myidx, e);
        acc += __half2float(g_q2h[(size_t)s * CLS + lane]);
    }
    for (e = 32; e < deg; e++)
        acc += __half2float(g_q2h[(size_t)g_col[start + e] * CLS + lane]);

    float v = fmaf(acc, g_dinv[node], b2[lane]);
    float m = v;
#pragma unroll
    for (int o = 16; o > 0; o >>= 1) m = fmaxf(m, __shfl_xor_sync(0xffffffffu, m, o));
    float ex = __expf(v - m);
    float ssum = ex;
#pragma unroll
    for (int o = 16; o > 0; o >>= 1) ssum += __shfl_xor_sync(0xffffffffu, ssum, o);
    out[(size_t)node * CLS + lane] = v - m - __logf(ssum);
}

// ---------------- launch -----------------------------------------------------
extern "C" void kernel_launch(void* const* d_in, const int* in_sizes, int n_in,
                              void* d_out, int out_size) {
    const float* X   = (const float*)d_in[0];
    const int*   ei  = (const int*)d_in[1];
    const float* W1  = (const float*)d_in[2];
    const float* b1  = (const float*)d_in[3];
    const float* W2  = (const float*)d_in[4];
    const float* b2  = (const float*)d_in[5];
    float*       out = (float*)d_out;

    cudaFuncSetAttribute(gemm1_mma, cudaFuncAttributeMaxDynamicSharedMemorySize,
                         SMEM_G1_BYTES);

    const int TB = 256;
    const int nodeGrid = (N_NODES + TB - 1) / TB;
    const int edgeGrid = (N_EDGES + TB - 1) / TB;
    const int convGrid = (F_IN * HID + TB - 1) / TB;
    const bool fork = g_s2 && g_e0 && g_e2;

    k_convw<<<convGrid, TB>>>(W1, W2);

    // fork: GEMM1 on side stream — independent of the degree chain
    if (fork) {
        cudaEventRecord(g_e0, 0);
        cudaStreamWaitEvent(g_s2, g_e0, 0);
        gemm1_mma<<<(N_NODES + BM - 1) / BM, 256, SMEM_G1_BYTES, g_s2>>>(X);
        cudaEventRecord(g_e2, g_s2);
    } else {
        gemm1_mma<<<(N_NODES + BM - 1) / BM, 256, SMEM_G1_BYTES>>>(X);
    }

    // degree + CSR chain on main stream (hidden under gemm1)
    k_zero_cnt   <<<nodeGrid, TB>>>(ei);
    k_cnt_scatter<<<edgeGrid, TB>>>(ei);
    k_scan1      <<<N_SBLK, SCAN_B>>>();
    k_scan2      <<<1, 256>>>();
    k_scan3      <<<nodeGrid, TB>>>();
    k_fill       <<<edgeGrid, TB>>>(ei);

    if (fork) cudaStreamWaitEvent(0, g_e2, 0);   // join before agg1

    k_agg1   <<<(N_NODES * 32 + TB - 1) / TB, TB>>>(b1);
    gemm2_mma<<<(N_NODES + 127) / 128, 256>>>();
    k_agg2   <<<(N_NODES * 32 + TB - 1) / TB, TB>>>(b2, out);
}